// round 11
// baseline (speedup 1.0000x reference)
#include <cuda_runtime.h>
#include <cuda_bf16.h>
#include <mma.h>
#include <cstdint>

using namespace nvcuda;

#define T_   512
#define B_   128
#define D_   512
#define H_   1024
#define G3H  3072

// ---- gi_gemm tiling (proven, verbatim) ----
#define MT   128
#define NT   64
#define KT   32
#define PADA 40
#define PADB 72

// ---- scan: 2 row-groups x 64 col-groups; CTA = [64 rows x 16 cols] ----
#define NCTA    128
#define RROWS   64
#define SKT     32
#define NCHUNK  (H_ / SKT)                  // 32
#define A_LD    40
#define APL_ELEMS (RROWS * A_LD)            // 2560
#define CHUNK_ELEMS (2 * APL_ELEMS)         // 5120 (hi+lo)
#define CHUNK_BYTES (CHUNK_ELEMS * 2)       // 10240
#define HGRP_ELEMS (NCHUNK * CHUNK_ELEMS)
#define B_LD    24
#define BHALF_BYTES (H_ * B_LD * 2)         // 49152
#define BPLANE_BYTES (2 * BHALF_BYTES)      // 98304
#define SM_W    0
#define SM_A    (2 * BPLANE_BYTES)          // 196608
#define SM_CTL  (SM_A + 3 * CHUNK_BYTES)    // 227328
#define SMEM_TOTAL (SM_CTL + 64)
#define NTHREADS 288                         // 8 consumer warps + 1 producer

__device__ __align__(256) float         g_Gi[(long long)T_ * B_ * G3H];
// h scratch: [pingpong][rowgroup][chunk][plane hi|lo][64][40]
__device__ __align__(256) __nv_bfloat16 g_h[2][2 * HGRP_ELEMS];
__device__ int      g_reset_mode;
// per-chunk ready counters (monotonic): [pingpong][rowgroup][chunk]
__device__ __align__(16) unsigned g_ready[2][2][NCHUNK];

// ---------------------------------------------------------------------------
__global__ void init_kernel(const unsigned char* __restrict__ resets) {
    const unsigned int* w = (const unsigned int*)resets;
    bool i32 = true, f32 = true;
    for (int i = 0; i < 16; i++) {
        unsigned int v = w[i];
        if (v != 0u && v != 1u) i32 = false;
        if (v != 0u && v != 0x3F800000u) f32 = false;
    }
    g_reset_mode = i32 ? 1 : (f32 ? 2 : 0);
    for (int rg = 0; rg < 2; rg++)
        for (int kc = 0; kc < NCHUNK; kc++) {
            g_ready[0][rg][kc] = 2u;   // prep_h counts as first write (2 writers)
            g_ready[1][rg][kc] = 0u;
        }
}

__device__ __forceinline__ bool get_reset_m(const void* r, int idx, int m) {
    if (m == 1) return ((const int*)r)[idx] != 0;
    if (m == 2) return ((const float*)r)[idx] != 0.0f;
    return ((const unsigned char*)r)[idx] != 0;
}

__device__ __forceinline__ void split2(float v, __nv_bfloat16& hi, __nv_bfloat16& lo) {
    hi = __float2bfloat16(v);
    lo = __float2bfloat16(v - __bfloat162float(hi));
}

__device__ __forceinline__ unsigned smem_u32(const void* p) {
    return (unsigned)__cvta_generic_to_shared(p);
}
__device__ __forceinline__ void mbar_init(unsigned a, unsigned c) {
    asm volatile("mbarrier.init.shared.b64 [%0], %1;" :: "r"(a), "r"(c) : "memory");
}
__device__ __forceinline__ void mbar_arrive(unsigned a) {
    asm volatile("mbarrier.arrive.shared.b64 _, [%0];" :: "r"(a) : "memory");
}
__device__ __forceinline__ void mbar_expect_tx(unsigned a, unsigned bytes) {
    asm volatile("mbarrier.arrive.expect_tx.shared.b64 _, [%0], %1;"
                 :: "r"(a), "r"(bytes) : "memory");
}
__device__ __forceinline__ void mbar_wait(unsigned a, unsigned parity) {
    asm volatile(
        "{\n\t.reg .pred P;\n\t"
        "W_%=:\n\t"
        "mbarrier.try_wait.parity.acquire.cta.shared::cta.b64 P, [%0], %1, 0x989680;\n\t"
        "@P bra D_%=;\n\t"
        "bra.uni W_%=;\n\t"
        "D_%=:\n\t}"
        :: "r"(a), "r"(parity) : "memory");
}
__device__ __forceinline__ void bulk_ld(unsigned dst, const void* src,
                                        unsigned bytes, unsigned mbar) {
    asm volatile(
        "cp.async.bulk.shared::cta.global.mbarrier::complete_tx::bytes [%0], [%1], %2, [%3];"
        :: "r"(dst), "l"(src), "r"(bytes), "r"(mbar) : "memory");
}
__device__ __forceinline__ uint4 ld_relaxed_v4(const unsigned* p) {
    uint4 v;
    asm volatile("ld.relaxed.gpu.global.v4.u32 {%0,%1,%2,%3}, [%4];"
                 : "=r"(v.x), "=r"(v.y), "=r"(v.z), "=r"(v.w) : "l"(p) : "memory");
    return v;
}
__device__ __forceinline__ void fence_acq_rel_gpu() {
    asm volatile("fence.acq_rel.gpu;" ::: "memory");
}

__device__ __forceinline__ void ldsm_x4(unsigned* r, unsigned a) {
    asm volatile("ldmatrix.sync.aligned.m8n8.x4.shared.b16 {%0,%1,%2,%3}, [%4];"
                 : "=r"(r[0]), "=r"(r[1]), "=r"(r[2]), "=r"(r[3]) : "r"(a));
}
__device__ __forceinline__ void ldsm_x2t(unsigned* r, unsigned a) {
    asm volatile("ldmatrix.sync.aligned.m8n8.x2.trans.shared.b16 {%0,%1}, [%2];"
                 : "=r"(r[0]), "=r"(r[1]) : "r"(a));
}
__device__ __forceinline__ void mma16816(float* c, const unsigned* a, const unsigned* b) {
    asm volatile(
        "mma.sync.aligned.m16n8k16.row.col.f32.bf16.bf16.f32 "
        "{%0,%1,%2,%3}, {%4,%5,%6,%7}, {%8,%9}, {%0,%1,%2,%3};"
        : "+f"(c[0]), "+f"(c[1]), "+f"(c[2]), "+f"(c[3])
        : "r"(a[0]), "r"(a[1]), "r"(a[2]), "r"(a[3]), "r"(b[0]), "r"(b[1]));
}

__global__ void prep_h_kernel(const float* __restrict__ h0,
                              const void* __restrict__ resets)
{
    int i = blockIdx.x * 256 + threadIdx.x;    // 0 .. B*H-1
    int b = i >> 10;
    int k = i & 1023;
    float v = get_reset_m(resets, b, g_reset_mode) ? 0.0f : h0[i];
    __nv_bfloat16 h, l; split2(v, h, l);
    int rg = b >> 6;
    int r  = b & 63;
    int o = rg * HGRP_ELEMS + (k >> 5) * CHUNK_ELEMS + r * A_LD + (k & 31);
    g_h[0][o] = h;
    g_h[0][o + APL_ELEMS] = l;
}

// ---------------------------------------------------------------------------
// Phase B: Gi = X @ Wi + bi  (proven, verbatim)
// ---------------------------------------------------------------------------
__global__ __launch_bounds__(256) void gi_gemm_kernel(
    const float* __restrict__ X,
    const float* __restrict__ Wi,
    const float* __restrict__ bi)
{
    __shared__ __align__(16) __nv_bfloat16 sAh[MT * PADA], sAl[MT * PADA];
    __shared__ __align__(16) __nv_bfloat16 sBh[KT * PADB], sBl[KT * PADB];
    __shared__ __align__(16) float sBias[16 * NT];

    const int n0  = blockIdx.x * NT;
    const long long m0 = (long long)blockIdx.y * MT;
    const int tid  = threadIdx.x;
    const int warp = tid >> 5;
    const int wm   = warp & 3;
    const int wn   = warp >> 2;

    for (int i = tid; i < 16 * NT; i += 256) sBias[i] = bi[n0 + (i % NT)];
    __syncthreads();

    wmma::fragment<wmma::accumulator, 16, 16, 16, float> acc[2][2];
    for (int i = 0; i < 2; i++)
        for (int j = 0; j < 2; j++)
            wmma::load_matrix_sync(acc[i][j], &sBias[wn * 32 + j * 16], NT,
                                   wmma::mem_row_major);

    for (int k0 = 0; k0 < D_; k0 += KT) {
        __syncthreads();
        for (int i = tid; i < MT * KT / 4; i += 256) {
            int r = i >> 3;
            int c = (i & 7) * 4;
            float4 v = *(const float4*)(X + (m0 + r) * D_ + k0 + c);
            float vs[4] = {v.x, v.y, v.z, v.w};
            #pragma unroll
            for (int q = 0; q < 4; q++) {
                __nv_bfloat16 h, l; split2(vs[q], h, l);
                sAh[r * PADA + c + q] = h;
                sAl[r * PADA + c + q] = l;
            }
        }
        for (int i = tid; i < KT * NT / 4; i += 256) {
            int r = i >> 4;
            int c = (i & 15) * 4;
            float4 v = *(const float4*)(Wi + (long long)(k0 + r) * G3H + n0 + c);
            float vs[4] = {v.x, v.y, v.z, v.w};
            #pragma unroll
            for (int q = 0; q < 4; q++) {
                __nv_bfloat16 h, l; split2(vs[q], h, l);
                sBh[r * PADB + c + q] = h;
                sBl[r * PADB + c + q] = l;
            }
        }
        __syncthreads();

        #pragma unroll
        for (int kk = 0; kk < KT; kk += 16) {
            wmma::fragment<wmma::matrix_a, 16, 16, 16, __nv_bfloat16, wmma::row_major> ah[2], al[2];
            wmma::fragment<wmma::matrix_b, 16, 16, 16, __nv_bfloat16, wmma::row_major> bh[2], bl[2];
            #pragma unroll
            for (int i = 0; i < 2; i++) {
                wmma::load_matrix_sync(ah[i], &sAh[(wm * 32 + i * 16) * PADA + kk], PADA);
                wmma::load_matrix_sync(al[i], &sAl[(wm * 32 + i * 16) * PADA + kk], PADA);
            }
            #pragma unroll
            for (int j = 0; j < 2; j++) {
                wmma::load_matrix_sync(bh[j], &sBh[kk * PADB + wn * 32 + j * 16], PADB);
                wmma::load_matrix_sync(bl[j], &sBl[kk * PADB + wn * 32 + j * 16], PADB);
            }
            #pragma unroll
            for (int i = 0; i < 2; i++)
                #pragma unroll
                for (int j = 0; j < 2; j++) {
                    wmma::mma_sync(acc[i][j], al[i], bh[j], acc[i][j]);
                    wmma::mma_sync(acc[i][j], ah[i], bl[j], acc[i][j]);
                    wmma::mma_sync(acc[i][j], ah[i], bh[j], acc[i][j]);
                }
        }
    }

    for (int i = 0; i < 2; i++)
        for (int j = 0; j < 2; j++) {
            float* p = g_Gi + (m0 + wm * 32 + i * 16) * G3H + n0 + wn * 32 + j * 16;
            wmma::store_matrix_sync(p, acc[i][j], G3H, wmma::mem_row_major);
        }
}

// ---------------------------------------------------------------------------
// Persistent scan: 128 CTAs x 288 threads, NO grid barrier.
// Warps 0-7 consumers (wm=wid&3 m16 tile, nh=wid>>2 B half), warp 8 producer.
// Cross-CTA sync: per-chunk monotonic ready counters (2 writers per chunk);
// producer gates each chunk's TMA on counter >= 2*(t/2+1).
// ---------------------------------------------------------------------------
__global__ __launch_bounds__(NTHREADS, 1) void scan_kernel(
    const float* __restrict__ Wh,
    const float* __restrict__ bhn,
    const void*  __restrict__ resets,
    float*       __restrict__ out)
{
    extern __shared__ __align__(128) char sm[];
    __nv_bfloat16* sW = (__nv_bfloat16*)(sm + SM_W);
    const unsigned sW_u32 = smem_u32(sm + SM_W);
    const unsigned sA_u32 = smem_u32(sm + SM_A);
    const unsigned ctl      = smem_u32(sm + SM_CTL);
    const unsigned mb_full  = ctl;
    const unsigned mb_empty = ctl + 24;

    const int tid = threadIdx.x;
    const int wid = tid >> 5;
    const int lid = tid & 31;
    const int bid = blockIdx.x;
    const int rg  = bid >> 6;
    const int j0  = (bid & 63) * 16;
    const int rmode = g_reset_mode;

    // ---- load resident Wh slice: 48 packed cols = 2 halves x (3 gates x 8)
    for (int idx = tid; idx < H_ * 48; idx += NTHREADS) {
        int k = idx / 48;
        int c = idx - k * 48;
        int h = c >= 24;
        int cr = c - h * 24;
        int g  = cr >> 3;
        int cj = cr & 7;
        float v = Wh[(long long)k * G3H + g * H_ + j0 + h * 8 + cj];
        __nv_bfloat16 hh, ll; split2(v, hh, ll);
        int eo = h * (H_ * B_LD) + k * B_LD + cr;
        sW[eo] = hh;
        sW[(BPLANE_BYTES / 2) + eo] = ll;
    }

    if (tid == 0) {
        #pragma unroll
        for (int i = 0; i < 3; i++) {
            mbar_init(mb_full + i * 8, 1);
            mbar_init(mb_empty + i * 8, 8);
        }
    }
    __syncthreads();
    if (tid < 8) {
        #pragma unroll
        for (int i = 0; i < 3; i++) mbar_arrive(mb_empty + i * 8);
    }
    asm volatile("fence.proxy.async;" ::: "memory");
    __syncthreads();

    // consumer geometry
    const int wm = wid & 3;               // m16 tile (rows wm*16..+16 of 64)
    const int nh = (wid >> 2) & 1;        // B half (cols j0+nh*8..+8)
    const unsigned a_off = (unsigned)((wm * 16 + (lid & 15)) * 80 + (lid >> 4) * 16);
    const unsigned b_half = (unsigned)(nh * BHALF_BYTES);
    const unsigned b_lane = (unsigned)((lid & 15) * 48);

    // epilogue coords (all consumer warps)
    const int r0l = wm * 16 + (lid >> 2);
    const int r1l = r0l + 8;
    const int grow0 = rg * 64 + r0l;
    const int grow1 = rg * 64 + r1l;
    const int col = j0 + nh * 8 + (lid & 3) * 2;
    const int hb0 = (col >> 5) * CHUNK_ELEMS + r0l * A_LD + (col & 31);
    const int hb1 = (col >> 5) * CHUNK_ELEMS + r1l * A_LD + (col & 31);
    const int mychunk = j0 >> 5;          // chunk this CTA's cols live in
    float bj0 = bhn[col], bj1 = bhn[col + 1];

    unsigned ph_empty = 0;                // producer state
    unsigned ph_full  = 0;                // per-consumer-warp state

    for (int t = 0; t < T_; t++) {
        const __nv_bfloat16* hsrc = g_h[t & 1] + rg * HGRP_ELEMS;
        __nv_bfloat16* hdst = g_h[(t + 1) & 1] + rg * HGRP_ELEMS;

        if (wid == 8) {
            // ---- producer: gate each chunk's TMA on its ready counter
            if (lid == 0) {
                const char* src = (const char*)g_h[t & 1] + (long long)rg * HGRP_ELEMS * 2;
                const unsigned target = 2u * (unsigned)(t / 2 + 1);
                const unsigned* cnt = &g_ready[t & 1][rg][0];
                for (int gp = 0; gp < NCHUNK / 4; gp++) {
                    // batched readiness poll (4 chunks per 16B load)
                    for (;;) {
                        uint4 c = ld_relaxed_v4(cnt + gp * 4);
                        if (c.x >= target && c.y >= target &&
                            c.z >= target && c.w >= target) break;
                        __nanosleep(32);
                    }
                    fence_acq_rel_gpu();
                    #pragma unroll
                    for (int j = 0; j < 4; j++) {
                        int kc = gp * 4 + j;
                        int buf = kc - (kc / 3) * 3;
                        mbar_wait(mb_empty + buf * 8, (ph_empty >> buf) & 1u);
                        ph_empty ^= 1u << buf;
                        mbar_expect_tx(mb_full + buf * 8, CHUNK_BYTES);
                        bulk_ld(sA_u32 + buf * CHUNK_BYTES,
                                src + (long long)kc * CHUNK_BYTES,
                                CHUNK_BYTES, mb_full + buf * 8);
                    }
                }
            }
        } else {
            // ---- epilogue input prefetch (before mainloop; R8-proven)
            const float* gp0 = g_Gi + (long long)t * B_ * G3H + (long long)grow0 * G3H + col;
            const float* gp1 = g_Gi + (long long)t * B_ * G3H + (long long)grow1 * G3H + col;
            float2 gr0 = __ldcs((const float2*)gp0);
            float2 gz0 = __ldcs((const float2*)(gp0 + H_));
            float2 gn0 = __ldcs((const float2*)(gp0 + 2 * H_));
            float2 gr1 = __ldcs((const float2*)gp1);
            float2 gz1 = __ldcs((const float2*)(gp1 + H_));
            float2 gn1 = __ldcs((const float2*)(gp1 + 2 * H_));
            unsigned hh0 = __ldcg((const unsigned*)(hsrc + hb0));
            unsigned hl0 = __ldcg((const unsigned*)(hsrc + hb0 + APL_ELEMS));
            unsigned hh1 = __ldcg((const unsigned*)(hsrc + hb1));
            unsigned hl1 = __ldcg((const unsigned*)(hsrc + hb1 + APL_ELEMS));
            bool rstA = (t + 1 < T_) ? get_reset_m(resets, (t + 1) * B_ + grow0, rmode) : false;
            bool rstB = (t + 1 < T_) ? get_reset_m(resets, (t + 1) * B_ + grow1, rmode) : false;

            // ---- mainloop: all 32 chunks, 9 independent accumulator chains
            float acc[9][4];
            #pragma unroll
            for (int i = 0; i < 9; i++)
                #pragma unroll
                for (int q = 0; q < 4; q++) acc[i][q] = 0.0f;

            for (int kc = 0; kc < NCHUNK; kc++) {
                const int buf = kc - (kc / 3) * 3;
                mbar_wait(mb_full + buf * 8, (ph_full >> buf) & 1u);
                ph_full ^= 1u << buf;

                const unsigned aB = sA_u32 + buf * CHUNK_BYTES;
                #pragma unroll
                for (int kk = 0; kk < 2; kk++) {
                    unsigned ah[4], al[4];
                    ldsm_x4(ah, aB + a_off + kk * 32);
                    ldsm_x4(al, aB + CHUNK_BYTES / 2 + a_off + kk * 32);
                    unsigned bbase = sW_u32 + b_half +
                                     (unsigned)(kc * 32 + kk * 16) * 48u + b_lane;
                    #pragma unroll
                    for (int tn = 0; tn < 3; tn++) {
                        unsigned bh[2], bl[2];
                        ldsm_x2t(bh, bbase + tn * 16);
                        ldsm_x2t(bl, bbase + tn * 16 + BPLANE_BYTES);
                        mma16816(acc[tn * 3 + 0], al, bh);
                        mma16816(acc[tn * 3 + 1], ah, bl);
                        mma16816(acc[tn * 3 + 2], ah, bh);
                    }
                }
                if (lid == 0) mbar_arrive(mb_empty + buf * 8);
            }

            float gh[3][4];
            #pragma unroll
            for (int tn = 0; tn < 3; tn++)
                #pragma unroll
                for (int q = 0; q < 4; q++)
                    gh[tn][q] = acc[tn * 3][q] + acc[tn * 3 + 1][q] + acc[tn * 3 + 2][q];

            // ---- epilogue (register-local)
            float hpA0 = __bfloat162float(__ushort_as_bfloat16((unsigned short)hh0))
                       + __bfloat162float(__ushort_as_bfloat16((unsigned short)hl0));
            float hpA1 = __bfloat162float(__ushort_as_bfloat16((unsigned short)(hh0 >> 16)))
                       + __bfloat162float(__ushort_as_bfloat16((unsigned short)(hl0 >> 16)));
            float hpB0 = __bfloat162float(__ushort_as_bfloat16((unsigned short)hh1))
                       + __bfloat162float(__ushort_as_bfloat16((unsigned short)hl1));
            float hpB1 = __bfloat162float(__ushort_as_bfloat16((unsigned short)(hh1 >> 16)))
                       + __bfloat162float(__ushort_as_bfloat16((unsigned short)(hl1 >> 16)));

            float hA0, hA1, hB0, hB1;
            {
                float r = 1.f / (1.f + __expf(-(gr0.x + gh[0][0])));
                float z = 1.f / (1.f + __expf(-(gz0.x + gh[1][0])));
                float n = tanhf(gn0.x + r * (gh[2][0] + bj0));
                hA0 = (1.f - z) * n + z * hpA0;
            }
            {
                float r = 1.f / (1.f + __expf(-(gr0.y + gh[0][1])));
                float z = 1.f / (1.f + __expf(-(gz0.y + gh[1][1])));
                float n = tanhf(gn0.y + r * (gh[2][1] + bj1));
                hA1 = (1.f - z) * n + z * hpA1;
            }
            {
                float r = 1.f / (1.f + __expf(-(gr1.x + gh[0][2])));
                float z = 1.f / (1.f + __expf(-(gz1.x + gh[1][2])));
                float n = tanhf(gn1.x + r * (gh[2][2] + bj0));
                hB0 = (1.f - z) * n + z * hpB0;
            }
            {
                float r = 1.f / (1.f + __expf(-(gr1.y + gh[0][3])));
                float z = 1.f / (1.f + __expf(-(gz1.y + gh[1][3])));
                float n = tanhf(gn1.y + r * (gh[2][3] + bj1));
                hB1 = (1.f - z) * n + z * hpB1;
            }

            float* outp = out + (long long)t * B_ * H_;
            *(float2*)(outp + (long long)grow0 * H_ + col) = make_float2(hA0, hA1);
            *(float2*)(outp + (long long)grow1 * H_ + col) = make_float2(hB0, hB1);

            if (t + 1 < T_) {
                float mA0 = rstA ? 0.f : hA0, mA1 = rstA ? 0.f : hA1;
                float mB0 = rstB ? 0.f : hB0, mB1 = rstB ? 0.f : hB1;
                __nv_bfloat16 h0a, l0a, h0b, l0b, h1a, l1a, h1b, l1b;
                split2(mA0, h0a, l0a); split2(mA1, h0b, l0b);
                split2(mB0, h1a, l1a); split2(mB1, h1b, l1b);
                *(unsigned*)(hdst + hb0) =
                    (unsigned)__bfloat16_as_ushort(h0a) | ((unsigned)__bfloat16_as_ushort(h0b) << 16);
                *(unsigned*)(hdst + hb0 + APL_ELEMS) =
                    (unsigned)__bfloat16_as_ushort(l0a) | ((unsigned)__bfloat16_as_ushort(l0b) << 16);
                *(unsigned*)(hdst + hb1) =
                    (unsigned)__bfloat16_as_ushort(h1a) | ((unsigned)__bfloat16_as_ushort(h1b) << 16);
                *(unsigned*)(hdst + hb1 + APL_ELEMS) =
                    (unsigned)__bfloat16_as_ushort(l1a) | ((unsigned)__bfloat16_as_ushort(l1b) << 16);

                // release this CTA's slice: fence each writer, sync consumers,
                // single +1 to the chunk counter (2 writer CTAs per chunk)
                __threadfence();
                asm volatile("bar.sync 1, 256;" ::: "memory");
                if (tid == 0)
                    atomicAdd(&g_ready[(t + 1) & 1][rg][mychunk], 1u);
            }
        }
        // no grid barrier: CTAs pipeline across steps via ready counters
    }
}

// ---------------------------------------------------------------------------
extern "C" void kernel_launch(void* const* d_in, const int* in_sizes, int n_in,
                              void* d_out, int out_size)
{
    const float* x      = (const float*)d_in[0];
    const void*  resets = d_in[1];
    const float* h0     = (const float*)d_in[2];
    const float* Wi     = (const float*)d_in[3];
    const float* bi     = (const float*)d_in[4];
    const float* Wh     = (const float*)d_in[5];
    const float* bhn    = (const float*)d_in[6];
    float* out = (float*)d_out;

    cudaFuncSetAttribute(scan_kernel, cudaFuncAttributeMaxDynamicSharedMemorySize,
                         SMEM_TOTAL);

    init_kernel<<<1, 1>>>((const unsigned char*)resets);
    prep_h_kernel<<<(B_ * H_) / 256, 256>>>(h0, resets);
    gi_gemm_kernel<<<dim3(G3H / NT, (T_ * B_) / MT), 256>>>(x, Wi, bi);
    scan_kernel<<<NCTA, NTHREADS, SMEM_TOTAL>>>(Wh, bhn, resets, out);
}

// round 12
// speedup vs baseline: 1.3708x; 1.3708x over previous
#include <cuda_runtime.h>
#include <cuda_bf16.h>
#include <cuda_fp16.h>
#include <mma.h>
#include <cstdint>

using namespace nvcuda;

#define T_   512
#define B_   128
#define D_   512
#define H_   1024
#define G3H  3072

// ---- gi_gemm tiling (proven, verbatim) ----
#define MT   128
#define NT   64
#define KT   32
#define PADA 40
#define PADB 72

// ---- scan: 2 row-groups x 64 col-groups; CTA = [64 rows x 16 cols], fp16 ----
#define NCTA    128
#define RROWS   64
#define SKT     32
#define NCHUNK  (H_ / SKT)                  // 32
#define NRING   4
#define A_LD    40
#define APL_ELEMS (RROWS * A_LD)            // 2560 fp16 elems
#define CHUNK_ELEMS APL_ELEMS               // single plane
#define CHUNK_BYTES (CHUNK_ELEMS * 2)       // 5120
#define HGRP_ELEMS (NCHUNK * CHUNK_ELEMS)
#define B_LD    24
#define BHALF_BYTES (H_ * B_LD * 2)         // 49152 (fp16, single plane)
#define SM_W    0
#define SM_A    (2 * BHALF_BYTES)           // 98304
#define SM_CTL  (SM_A + NRING * CHUNK_BYTES) // 118784
#define SMEM_TOTAL (SM_CTL + 64)
#define NTHREADS 288                         // 8 consumer warps + 1 producer

__device__ __align__(256) float  g_Gi[(long long)T_ * B_ * G3H];
// h scratch: [pingpong][rowgroup][chunk][64][40] fp16
__device__ __align__(256) __half g_h[2][2 * HGRP_ELEMS];
__device__ int      g_reset_mode;
__device__ unsigned g_bar;

// ---------------------------------------------------------------------------
__global__ void init_kernel(const unsigned char* __restrict__ resets) {
    const unsigned int* w = (const unsigned int*)resets;
    bool i32 = true, f32 = true;
    for (int i = 0; i < 16; i++) {
        unsigned int v = w[i];
        if (v != 0u && v != 1u) i32 = false;
        if (v != 0u && v != 0x3F800000u) f32 = false;
    }
    g_reset_mode = i32 ? 1 : (f32 ? 2 : 0);
    g_bar = 0u;
}

__device__ __forceinline__ bool get_reset_m(const void* r, int idx, int m) {
    if (m == 1) return ((const int*)r)[idx] != 0;
    if (m == 2) return ((const float*)r)[idx] != 0.0f;
    return ((const unsigned char*)r)[idx] != 0;
}

__device__ __forceinline__ void split2(float v, __nv_bfloat16& hi, __nv_bfloat16& lo) {
    hi = __float2bfloat16(v);
    lo = __float2bfloat16(v - __bfloat162float(hi));
}

__device__ __forceinline__ unsigned smem_u32(const void* p) {
    return (unsigned)__cvta_generic_to_shared(p);
}
__device__ __forceinline__ void mbar_init(unsigned a, unsigned c) {
    asm volatile("mbarrier.init.shared.b64 [%0], %1;" :: "r"(a), "r"(c) : "memory");
}
__device__ __forceinline__ void mbar_arrive(unsigned a) {
    asm volatile("mbarrier.arrive.shared.b64 _, [%0];" :: "r"(a) : "memory");
}
__device__ __forceinline__ void mbar_expect_tx(unsigned a, unsigned bytes) {
    asm volatile("mbarrier.arrive.expect_tx.shared.b64 _, [%0], %1;"
                 :: "r"(a), "r"(bytes) : "memory");
}
__device__ __forceinline__ void mbar_wait(unsigned a, unsigned parity) {
    asm volatile(
        "{\n\t.reg .pred P;\n\t"
        "W_%=:\n\t"
        "mbarrier.try_wait.parity.acquire.cta.shared::cta.b64 P, [%0], %1, 0x989680;\n\t"
        "@P bra D_%=;\n\t"
        "bra.uni W_%=;\n\t"
        "D_%=:\n\t}"
        :: "r"(a), "r"(parity) : "memory");
}
__device__ __forceinline__ void bulk_ld(unsigned dst, const void* src,
                                        unsigned bytes, unsigned mbar) {
    asm volatile(
        "cp.async.bulk.shared::cta.global.mbarrier::complete_tx::bytes [%0], [%1], %2, [%3];"
        :: "r"(dst), "l"(src), "r"(bytes), "r"(mbar) : "memory");
}

__device__ __forceinline__ void ldsm_x4(unsigned* r, unsigned a) {
    asm volatile("ldmatrix.sync.aligned.m8n8.x4.shared.b16 {%0,%1,%2,%3}, [%4];"
                 : "=r"(r[0]), "=r"(r[1]), "=r"(r[2]), "=r"(r[3]) : "r"(a));
}
__device__ __forceinline__ void ldsm_x2t(unsigned* r, unsigned a) {
    asm volatile("ldmatrix.sync.aligned.m8n8.x2.trans.shared.b16 {%0,%1}, [%2];"
                 : "=r"(r[0]), "=r"(r[1]) : "r"(a));
}
__device__ __forceinline__ void mma16816h(float* c, const unsigned* a, const unsigned* b) {
    asm volatile(
        "mma.sync.aligned.m16n8k16.row.col.f32.f16.f16.f32 "
        "{%0,%1,%2,%3}, {%4,%5,%6,%7}, {%8,%9}, {%0,%1,%2,%3};"
        : "+f"(c[0]), "+f"(c[1]), "+f"(c[2]), "+f"(c[3])
        : "r"(a[0]), "r"(a[1]), "r"(a[2]), "r"(a[3]), "r"(b[0]), "r"(b[1]));
}

__global__ void prep_h_kernel(const float* __restrict__ h0,
                              const void* __restrict__ resets)
{
    int i = blockIdx.x * 256 + threadIdx.x;    // 0 .. B*H-1
    int b = i >> 10;
    int k = i & 1023;
    float v = get_reset_m(resets, b, g_reset_mode) ? 0.0f : h0[i];
    int rg = b >> 6;
    int r  = b & 63;
    int o = rg * HGRP_ELEMS + (k >> 5) * CHUNK_ELEMS + r * A_LD + (k & 31);
    g_h[0][o] = __float2half_rn(v);
}

// ---------------------------------------------------------------------------
// Phase B: Gi = X @ Wi + bi  (proven bf16x3, verbatim)
// ---------------------------------------------------------------------------
__global__ __launch_bounds__(256) void gi_gemm_kernel(
    const float* __restrict__ X,
    const float* __restrict__ Wi,
    const float* __restrict__ bi)
{
    __shared__ __align__(16) __nv_bfloat16 sAh[MT * PADA], sAl[MT * PADA];
    __shared__ __align__(16) __nv_bfloat16 sBh[KT * PADB], sBl[KT * PADB];
    __shared__ __align__(16) float sBias[16 * NT];

    const int n0  = blockIdx.x * NT;
    const long long m0 = (long long)blockIdx.y * MT;
    const int tid  = threadIdx.x;
    const int warp = tid >> 5;
    const int wm   = warp & 3;
    const int wn   = warp >> 2;

    for (int i = tid; i < 16 * NT; i += 256) sBias[i] = bi[n0 + (i % NT)];
    __syncthreads();

    wmma::fragment<wmma::accumulator, 16, 16, 16, float> acc[2][2];
    for (int i = 0; i < 2; i++)
        for (int j = 0; j < 2; j++)
            wmma::load_matrix_sync(acc[i][j], &sBias[wn * 32 + j * 16], NT,
                                   wmma::mem_row_major);

    for (int k0 = 0; k0 < D_; k0 += KT) {
        __syncthreads();
        for (int i = tid; i < MT * KT / 4; i += 256) {
            int r = i >> 3;
            int c = (i & 7) * 4;
            float4 v = *(const float4*)(X + (m0 + r) * D_ + k0 + c);
            float vs[4] = {v.x, v.y, v.z, v.w};
            #pragma unroll
            for (int q = 0; q < 4; q++) {
                __nv_bfloat16 h, l; split2(vs[q], h, l);
                sAh[r * PADA + c + q] = h;
                sAl[r * PADA + c + q] = l;
            }
        }
        for (int i = tid; i < KT * NT / 4; i += 256) {
            int r = i >> 4;
            int c = (i & 15) * 4;
            float4 v = *(const float4*)(Wi + (long long)(k0 + r) * G3H + n0 + c);
            float vs[4] = {v.x, v.y, v.z, v.w};
            #pragma unroll
            for (int q = 0; q < 4; q++) {
                __nv_bfloat16 h, l; split2(vs[q], h, l);
                sBh[r * PADB + c + q] = h;
                sBl[r * PADB + c + q] = l;
            }
        }
        __syncthreads();

        #pragma unroll
        for (int kk = 0; kk < KT; kk += 16) {
            wmma::fragment<wmma::matrix_a, 16, 16, 16, __nv_bfloat16, wmma::row_major> ah[2], al[2];
            wmma::fragment<wmma::matrix_b, 16, 16, 16, __nv_bfloat16, wmma::row_major> bh[2], bl[2];
            #pragma unroll
            for (int i = 0; i < 2; i++) {
                wmma::load_matrix_sync(ah[i], &sAh[(wm * 32 + i * 16) * PADA + kk], PADA);
                wmma::load_matrix_sync(al[i], &sAl[(wm * 32 + i * 16) * PADA + kk], PADA);
            }
            #pragma unroll
            for (int j = 0; j < 2; j++) {
                wmma::load_matrix_sync(bh[j], &sBh[kk * PADB + wn * 32 + j * 16], PADB);
                wmma::load_matrix_sync(bl[j], &sBl[kk * PADB + wn * 32 + j * 16], PADB);
            }
            #pragma unroll
            for (int i = 0; i < 2; i++)
                #pragma unroll
                for (int j = 0; j < 2; j++) {
                    wmma::mma_sync(acc[i][j], al[i], bh[j], acc[i][j]);
                    wmma::mma_sync(acc[i][j], ah[i], bl[j], acc[i][j]);
                    wmma::mma_sync(acc[i][j], ah[i], bh[j], acc[i][j]);
                }
        }
    }

    for (int i = 0; i < 2; i++)
        for (int j = 0; j < 2; j++) {
            float* p = g_Gi + (m0 + wm * 32 + i * 16) * G3H + n0 + wn * 32 + j * 16;
            wmma::store_matrix_sync(p, acc[i][j], G3H, wmma::mem_row_major);
        }
}

// ---------------------------------------------------------------------------
// Persistent scan (R10 structure, fp16x1 numerics): 128 CTAs x 288 threads.
// Warps 0-7 consumers (wm=wid&3 m16 tile, nh=wid>>2 B half), warp 8 producer.
// 4-deep TMA ring, grid barrier (proven atomic form).
// ---------------------------------------------------------------------------
__global__ __launch_bounds__(NTHREADS, 1) void scan_kernel(
    const float* __restrict__ Wh,
    const float* __restrict__ bhn,
    const void*  __restrict__ resets,
    float*       __restrict__ out)
{
    extern __shared__ __align__(128) char sm[];
    __half* sW = (__half*)(sm + SM_W);
    const unsigned sW_u32 = smem_u32(sm + SM_W);
    const unsigned sA_u32 = smem_u32(sm + SM_A);
    const unsigned ctl      = smem_u32(sm + SM_CTL);
    const unsigned mb_full  = ctl;        // 4 x 8B
    const unsigned mb_empty = ctl + 32;   // 4 x 8B

    const int tid = threadIdx.x;
    const int wid = tid >> 5;
    const int lid = tid & 31;
    const int bid = blockIdx.x;
    const int rg  = bid >> 6;
    const int j0  = (bid & 63) * 16;
    const int rmode = g_reset_mode;

    // ---- load resident Wh slice: 48 packed cols (fp16, single plane)
    for (int idx = tid; idx < H_ * 48; idx += NTHREADS) {
        int k = idx / 48;
        int c = idx - k * 48;
        int h = c >= 24;
        int cr = c - h * 24;
        int g  = cr >> 3;
        int cj = cr & 7;
        float v = Wh[(long long)k * G3H + g * H_ + j0 + h * 8 + cj];
        sW[h * (H_ * B_LD) + k * B_LD + cr] = __float2half_rn(v);
    }

    if (tid == 0) {
        #pragma unroll
        for (int i = 0; i < NRING; i++) {
            mbar_init(mb_full + i * 8, 1);
            mbar_init(mb_empty + i * 8, 8);
        }
    }
    __syncthreads();
    if (tid < 8) {
        #pragma unroll
        for (int i = 0; i < NRING; i++) mbar_arrive(mb_empty + i * 8);
    }
    asm volatile("fence.proxy.async;" ::: "memory");
    __syncthreads();

    // consumer geometry
    const int wm = wid & 3;
    const int nh = (wid >> 2) & 1;
    const unsigned a_off = (unsigned)((wm * 16 + (lid & 15)) * 80 + (lid >> 4) * 16);
    const unsigned b_half = (unsigned)(nh * BHALF_BYTES);
    const unsigned b_lane = (unsigned)((lid & 15) * 48);

    // epilogue coords
    const int r0l = wm * 16 + (lid >> 2);
    const int r1l = r0l + 8;
    const int grow0 = rg * 64 + r0l;
    const int grow1 = rg * 64 + r1l;
    const int col = j0 + nh * 8 + (lid & 3) * 2;
    const int hb0 = (col >> 5) * CHUNK_ELEMS + r0l * A_LD + (col & 31);
    const int hb1 = (col >> 5) * CHUNK_ELEMS + r1l * A_LD + (col & 31);
    float bj0 = bhn[col], bj1 = bhn[col + 1];

    unsigned ph_empty = 0;                // producer state
    unsigned ph_full  = 0;                // per-consumer-warp state

    for (int t = 0; t < T_; t++) {
        const __half* hsrc = g_h[t & 1] + rg * HGRP_ELEMS;
        __half* hdst = g_h[(t + 1) & 1] + rg * HGRP_ELEMS;

        if (wid == 8) {
            if (lid == 0) {
                const char* src = (const char*)hsrc;
                for (int kc = 0; kc < NCHUNK; kc++) {
                    int buf = kc & (NRING - 1);
                    mbar_wait(mb_empty + buf * 8, (ph_empty >> buf) & 1u);
                    ph_empty ^= 1u << buf;
                    mbar_expect_tx(mb_full + buf * 8, CHUNK_BYTES);
                    bulk_ld(sA_u32 + buf * CHUNK_BYTES,
                            src + (long long)kc * CHUNK_BYTES,
                            CHUNK_BYTES, mb_full + buf * 8);
                }
            }
        } else {
            // ---- epilogue input prefetch
            const float* gp0 = g_Gi + (long long)t * B_ * G3H + (long long)grow0 * G3H + col;
            const float* gp1 = g_Gi + (long long)t * B_ * G3H + (long long)grow1 * G3H + col;
            float2 gr0 = __ldcs((const float2*)gp0);
            float2 gz0 = __ldcs((const float2*)(gp0 + H_));
            float2 gn0 = __ldcs((const float2*)(gp0 + 2 * H_));
            float2 gr1 = __ldcs((const float2*)gp1);
            float2 gz1 = __ldcs((const float2*)(gp1 + H_));
            float2 gn1 = __ldcs((const float2*)(gp1 + 2 * H_));
            unsigned hh0 = __ldcg((const unsigned*)(hsrc + hb0));
            unsigned hh1 = __ldcg((const unsigned*)(hsrc + hb1));
            bool rstA = (t + 1 < T_) ? get_reset_m(resets, (t + 1) * B_ + grow0, rmode) : false;
            bool rstB = (t + 1 < T_) ? get_reset_m(resets, (t + 1) * B_ + grow1, rmode) : false;

            // ---- mainloop: 32 chunks, 6 independent chains (3 gates x 2 kk)
            float acc[6][4];
            #pragma unroll
            for (int i = 0; i < 6; i++)
                #pragma unroll
                for (int q = 0; q < 4; q++) acc[i][q] = 0.0f;

            for (int kc = 0; kc < NCHUNK; kc++) {
                const int buf = kc & (NRING - 1);
                mbar_wait(mb_full + buf * 8, (ph_full >> buf) & 1u);
                ph_full ^= 1u << buf;

                const unsigned aB = sA_u32 + buf * CHUNK_BYTES;
                #pragma unroll
                for (int kk = 0; kk < 2; kk++) {
                    unsigned ah[4];
                    ldsm_x4(ah, aB + a_off + kk * 32);
                    unsigned bbase = sW_u32 + b_half +
                                     (unsigned)(kc * 32 + kk * 16) * 48u + b_lane;
                    #pragma unroll
                    for (int tn = 0; tn < 3; tn++) {
                        unsigned bh[2];
                        ldsm_x2t(bh, bbase + tn * 16);
                        mma16816h(acc[tn * 2 + kk], ah, bh);
                    }
                }
                if (lid == 0) mbar_arrive(mb_empty + buf * 8);
            }

            float gh[3][4];
            #pragma unroll
            for (int tn = 0; tn < 3; tn++)
                #pragma unroll
                for (int q = 0; q < 4; q++)
                    gh[tn][q] = acc[tn * 2][q] + acc[tn * 2 + 1][q];

            // ---- epilogue (register-local)
            __half2 hv0 = *reinterpret_cast<__half2*>(&hh0);
            __half2 hv1 = *reinterpret_cast<__half2*>(&hh1);
            float2 hpA = __half22float2(hv0);
            float2 hpB = __half22float2(hv1);

            float hA0, hA1, hB0, hB1;
            {
                float r = 1.f / (1.f + __expf(-(gr0.x + gh[0][0])));
                float z = 1.f / (1.f + __expf(-(gz0.x + gh[1][0])));
                float n = tanhf(gn0.x + r * (gh[2][0] + bj0));
                hA0 = (1.f - z) * n + z * hpA.x;
            }
            {
                float r = 1.f / (1.f + __expf(-(gr0.y + gh[0][1])));
                float z = 1.f / (1.f + __expf(-(gz0.y + gh[1][1])));
                float n = tanhf(gn0.y + r * (gh[2][1] + bj1));
                hA1 = (1.f - z) * n + z * hpA.y;
            }
            {
                float r = 1.f / (1.f + __expf(-(gr1.x + gh[0][2])));
                float z = 1.f / (1.f + __expf(-(gz1.x + gh[1][2])));
                float n = tanhf(gn1.x + r * (gh[2][2] + bj0));
                hB0 = (1.f - z) * n + z * hpB.x;
            }
            {
                float r = 1.f / (1.f + __expf(-(gr1.y + gh[0][3])));
                float z = 1.f / (1.f + __expf(-(gz1.y + gh[1][3])));
                float n = tanhf(gn1.y + r * (gh[2][3] + bj1));
                hB1 = (1.f - z) * n + z * hpB.y;
            }

            float* outp = out + (long long)t * B_ * H_;
            *(float2*)(outp + (long long)grow0 * H_ + col) = make_float2(hA0, hA1);
            *(float2*)(outp + (long long)grow1 * H_ + col) = make_float2(hB0, hB1);

            if (t + 1 < T_) {
                float mA0 = rstA ? 0.f : hA0, mA1 = rstA ? 0.f : hA1;
                float mB0 = rstB ? 0.f : hB0, mB1 = rstB ? 0.f : hB1;
                __half2 sv0 = __floats2half2_rn(mA0, mA1);
                __half2 sv1 = __floats2half2_rn(mB0, mB1);
                *(unsigned*)(hdst + hb0) = *reinterpret_cast<unsigned*>(&sv0);
                *(unsigned*)(hdst + hb1) = *reinterpret_cast<unsigned*>(&sv1);
            }
        }

        // ---- grid barrier (proven)
        __threadfence();
        __syncthreads();
        if (tid == 0) {
            atomicAdd(&g_bar, 1u);
            unsigned target = (unsigned)gridDim.x * (unsigned)(t + 1);
            unsigned v;
            do {
                asm volatile("ld.acquire.gpu.u32 %0, [%1];" : "=r"(v) : "l"(&g_bar));
                if (v < target) __nanosleep(32);
            } while (v < target);
        }
        __syncthreads();
    }
}

// ---------------------------------------------------------------------------
extern "C" void kernel_launch(void* const* d_in, const int* in_sizes, int n_in,
                              void* d_out, int out_size)
{
    const float* x      = (const float*)d_in[0];
    const void*  resets = d_in[1];
    const float* h0     = (const float*)d_in[2];
    const float* Wi     = (const float*)d_in[3];
    const float* bi     = (const float*)d_in[4];
    const float* Wh     = (const float*)d_in[5];
    const float* bhn    = (const float*)d_in[6];
    float* out = (float*)d_out;

    cudaFuncSetAttribute(scan_kernel, cudaFuncAttributeMaxDynamicSharedMemorySize,
                         SMEM_TOTAL);

    init_kernel<<<1, 1>>>((const unsigned char*)resets);
    prep_h_kernel<<<(B_ * H_) / 256, 256>>>(h0, resets);
    gi_gemm_kernel<<<dim3(G3H / NT, (T_ * B_) / MT), 256>>>(x, Wi, bi);
    scan_kernel<<<NCTA, NTHREADS, SMEM_TOTAL>>>(Wh, bhn, resets, out);
}

// round 13
// speedup vs baseline: 2.1715x; 1.5841x over previous
#include <cuda_runtime.h>
#include <cuda_bf16.h>
#include <cuda_fp16.h>
#include <mma.h>
#include <cstdint>

using namespace nvcuda;

#define T_   512
#define B_   128
#define D_   512
#define H_   1024
#define G3H  3072

// ---- gi_gemm tiling (structure proven; fp16 single-plane) ----
#define MT   128
#define NT   64
#define KT   32
#define PADA 40
#define PADB 72

// ---- scan: 2 row-groups x 64 col-groups; CTA = [64 rows x 16 cols], fp16 ----
#define NCTA    128
#define RROWS   64
#define SKT     64
#define NCHUNK  (H_ / SKT)                  // 16
#define NRING   4
#define A_LD    72                          // fp16 elems/row (144B, conflict-free)
#define CHUNK_ELEMS (RROWS * A_LD)          // 4608
#define CHUNK_BYTES (CHUNK_ELEMS * 2)       // 9216
#define HGRP_ELEMS (NCHUNK * CHUNK_ELEMS)
#define B_LD    24
#define BHALF_BYTES (H_ * B_LD * 2)         // 49152
#define SM_W    0
#define SM_A    (2 * BHALF_BYTES)           // 98304
#define SM_CTL  (SM_A + NRING * CHUNK_BYTES) // 135168
#define SMEM_TOTAL (SM_CTL + 64)
#define NTHREADS 288

__device__ __align__(256) float  g_Gi[(long long)T_ * B_ * G3H];
// h scratch: [pingpong][rowgroup][chunk][64][72] fp16
__device__ __align__(256) __half g_h[2][2 * HGRP_ELEMS];
__device__ int      g_reset_mode;
__device__ unsigned g_bar;

// ---------------------------------------------------------------------------
__global__ void init_kernel(const unsigned char* __restrict__ resets) {
    const unsigned int* w = (const unsigned int*)resets;
    bool i32 = true, f32 = true;
    for (int i = 0; i < 16; i++) {
        unsigned int v = w[i];
        if (v != 0u && v != 1u) i32 = false;
        if (v != 0u && v != 0x3F800000u) f32 = false;
    }
    g_reset_mode = i32 ? 1 : (f32 ? 2 : 0);
    g_bar = 0u;
}

__device__ __forceinline__ bool get_reset_m(const void* r, int idx, int m) {
    if (m == 1) return ((const int*)r)[idx] != 0;
    if (m == 2) return ((const float*)r)[idx] != 0.0f;
    return ((const unsigned char*)r)[idx] != 0;
}

__device__ __forceinline__ unsigned smem_u32(const void* p) {
    return (unsigned)__cvta_generic_to_shared(p);
}
__device__ __forceinline__ void mbar_init(unsigned a, unsigned c) {
    asm volatile("mbarrier.init.shared.b64 [%0], %1;" :: "r"(a), "r"(c) : "memory");
}
__device__ __forceinline__ void mbar_arrive(unsigned a) {
    asm volatile("mbarrier.arrive.shared.b64 _, [%0];" :: "r"(a) : "memory");
}
__device__ __forceinline__ void mbar_expect_tx(unsigned a, unsigned bytes) {
    asm volatile("mbarrier.arrive.expect_tx.shared.b64 _, [%0], %1;"
                 :: "r"(a), "r"(bytes) : "memory");
}
__device__ __forceinline__ void mbar_wait(unsigned a, unsigned parity) {
    asm volatile(
        "{\n\t.reg .pred P;\n\t"
        "W_%=:\n\t"
        "mbarrier.try_wait.parity.acquire.cta.shared::cta.b64 P, [%0], %1, 0x989680;\n\t"
        "@P bra D_%=;\n\t"
        "bra.uni W_%=;\n\t"
        "D_%=:\n\t}"
        :: "r"(a), "r"(parity) : "memory");
}
__device__ __forceinline__ void bulk_ld(unsigned dst, const void* src,
                                        unsigned bytes, unsigned mbar) {
    asm volatile(
        "cp.async.bulk.shared::cta.global.mbarrier::complete_tx::bytes [%0], [%1], %2, [%3];"
        :: "r"(dst), "l"(src), "r"(bytes), "r"(mbar) : "memory");
}

__device__ __forceinline__ void ldsm_x4(unsigned* r, unsigned a) {
    asm volatile("ldmatrix.sync.aligned.m8n8.x4.shared.b16 {%0,%1,%2,%3}, [%4];"
                 : "=r"(r[0]), "=r"(r[1]), "=r"(r[2]), "=r"(r[3]) : "r"(a));
}
__device__ __forceinline__ void ldsm_x2t(unsigned* r, unsigned a) {
    asm volatile("ldmatrix.sync.aligned.m8n8.x2.trans.shared.b16 {%0,%1}, [%2];"
                 : "=r"(r[0]), "=r"(r[1]) : "r"(a));
}
__device__ __forceinline__ void mma16816h(float* c, const unsigned* a, const unsigned* b) {
    asm volatile(
        "mma.sync.aligned.m16n8k16.row.col.f32.f16.f16.f32 "
        "{%0,%1,%2,%3}, {%4,%5,%6,%7}, {%8,%9}, {%0,%1,%2,%3};"
        : "+f"(c[0]), "+f"(c[1]), "+f"(c[2]), "+f"(c[3])
        : "r"(a[0]), "r"(a[1]), "r"(a[2]), "r"(a[3]), "r"(b[0]), "r"(b[1]));
}

__global__ void prep_h_kernel(const float* __restrict__ h0,
                              const void* __restrict__ resets)
{
    int i = blockIdx.x * 256 + threadIdx.x;    // 0 .. B*H-1
    int b = i >> 10;
    int k = i & 1023;
    float v = get_reset_m(resets, b, g_reset_mode) ? 0.0f : h0[i];
    int rg = b >> 6;
    int r  = b & 63;
    int o = rg * HGRP_ELEMS + (k >> 6) * CHUNK_ELEMS + r * A_LD + (k & 63);
    g_h[0][o] = __float2half_rn(v);
}

// ---------------------------------------------------------------------------
// Phase B: Gi = X @ Wi + bi   (proven structure, fp16 single-plane)
// ---------------------------------------------------------------------------
__global__ __launch_bounds__(256) void gi_gemm_kernel(
    const float* __restrict__ X,
    const float* __restrict__ Wi,
    const float* __restrict__ bi)
{
    __shared__ __align__(16) __half sA[MT * PADA];
    __shared__ __align__(16) __half sB[KT * PADB];
    __shared__ __align__(16) float sBias[16 * NT];

    const int n0  = blockIdx.x * NT;
    const long long m0 = (long long)blockIdx.y * MT;
    const int tid  = threadIdx.x;
    const int warp = tid >> 5;
    const int wm   = warp & 3;
    const int wn   = warp >> 2;

    for (int i = tid; i < 16 * NT; i += 256) sBias[i] = bi[n0 + (i % NT)];
    __syncthreads();

    wmma::fragment<wmma::accumulator, 16, 16, 16, float> acc[2][2];
    for (int i = 0; i < 2; i++)
        for (int j = 0; j < 2; j++)
            wmma::load_matrix_sync(acc[i][j], &sBias[wn * 32 + j * 16], NT,
                                   wmma::mem_row_major);

    for (int k0 = 0; k0 < D_; k0 += KT) {
        __syncthreads();
        for (int i = tid; i < MT * KT / 4; i += 256) {
            int r = i >> 3;
            int c = (i & 7) * 4;
            float4 v = *(const float4*)(X + (m0 + r) * D_ + k0 + c);
            sA[r * PADA + c + 0] = __float2half_rn(v.x);
            sA[r * PADA + c + 1] = __float2half_rn(v.y);
            sA[r * PADA + c + 2] = __float2half_rn(v.z);
            sA[r * PADA + c + 3] = __float2half_rn(v.w);
        }
        for (int i = tid; i < KT * NT / 4; i += 256) {
            int r = i >> 4;
            int c = (i & 15) * 4;
            float4 v = *(const float4*)(Wi + (long long)(k0 + r) * G3H + n0 + c);
            sB[r * PADB + c + 0] = __float2half_rn(v.x);
            sB[r * PADB + c + 1] = __float2half_rn(v.y);
            sB[r * PADB + c + 2] = __float2half_rn(v.z);
            sB[r * PADB + c + 3] = __float2half_rn(v.w);
        }
        __syncthreads();

        #pragma unroll
        for (int kk = 0; kk < KT; kk += 16) {
            wmma::fragment<wmma::matrix_a, 16, 16, 16, __half, wmma::row_major> a[2];
            wmma::fragment<wmma::matrix_b, 16, 16, 16, __half, wmma::row_major> b[2];
            #pragma unroll
            for (int i = 0; i < 2; i++)
                wmma::load_matrix_sync(a[i], &sA[(wm * 32 + i * 16) * PADA + kk], PADA);
            #pragma unroll
            for (int j = 0; j < 2; j++)
                wmma::load_matrix_sync(b[j], &sB[kk * PADB + wn * 32 + j * 16], PADB);
            #pragma unroll
            for (int i = 0; i < 2; i++)
                #pragma unroll
                for (int j = 0; j < 2; j++)
                    wmma::mma_sync(acc[i][j], a[i], b[j], acc[i][j]);
        }
    }

    for (int i = 0; i < 2; i++)
        for (int j = 0; j < 2; j++) {
            float* p = g_Gi + (m0 + wm * 32 + i * 16) * G3H + n0 + wn * 32 + j * 16;
            wmma::store_matrix_sync(p, acc[i][j], G3H, wmma::mem_row_major);
        }
}

// ---------------------------------------------------------------------------
// Persistent scan (fp16x1): 128 CTAs x 288 threads, SKT=64 (16 chunks).
// hp carried in registers across steps; next-step gi prefetched before barrier.
// ---------------------------------------------------------------------------
__global__ __launch_bounds__(NTHREADS, 1) void scan_kernel(
    const float* __restrict__ Wh,
    const float* __restrict__ bhn,
    const void*  __restrict__ resets,
    float*       __restrict__ out)
{
    extern __shared__ __align__(128) char sm[];
    __half* sW = (__half*)(sm + SM_W);
    const unsigned sW_u32 = smem_u32(sm + SM_W);
    const unsigned sA_u32 = smem_u32(sm + SM_A);
    const unsigned ctl      = smem_u32(sm + SM_CTL);
    const unsigned mb_full  = ctl;        // 4 x 8B
    const unsigned mb_empty = ctl + 32;   // 4 x 8B

    const int tid = threadIdx.x;
    const int wid = tid >> 5;
    const int lid = tid & 31;
    const int bid = blockIdx.x;
    const int rg  = bid >> 6;
    const int j0  = (bid & 63) * 16;
    const int rmode = g_reset_mode;

    // ---- load resident Wh slice: 48 packed cols (fp16)
    for (int idx = tid; idx < H_ * 48; idx += NTHREADS) {
        int k = idx / 48;
        int c = idx - k * 48;
        int h = c >= 24;
        int cr = c - h * 24;
        int g  = cr >> 3;
        int cj = cr & 7;
        float v = Wh[(long long)k * G3H + g * H_ + j0 + h * 8 + cj];
        sW[h * (H_ * B_LD) + k * B_LD + cr] = __float2half_rn(v);
    }

    if (tid == 0) {
        #pragma unroll
        for (int i = 0; i < NRING; i++) {
            mbar_init(mb_full + i * 8, 1);
            mbar_init(mb_empty + i * 8, 8);
        }
    }
    __syncthreads();
    if (tid < 8) {
        #pragma unroll
        for (int i = 0; i < NRING; i++) mbar_arrive(mb_empty + i * 8);
    }
    asm volatile("fence.proxy.async;" ::: "memory");
    __syncthreads();

    // consumer geometry (SKT=64: 144B A rows, kk 0..3)
    const int wm = wid & 3;
    const int nh = (wid >> 2) & 1;
    const unsigned a_off = (unsigned)((wm * 16 + (lid & 15)) * 144 + (lid >> 4) * 16);
    const unsigned b_half = (unsigned)(nh * BHALF_BYTES);
    const unsigned b_lane = (unsigned)((lid & 15) * 48);

    // epilogue coords
    const int r0l = wm * 16 + (lid >> 2);
    const int r1l = r0l + 8;
    const int grow0 = rg * 64 + r0l;
    const int grow1 = rg * 64 + r1l;
    const int col = j0 + nh * 8 + (lid & 3) * 2;
    const int hb0 = (col >> 6) * CHUNK_ELEMS + r0l * A_LD + (col & 63);
    const int hb1 = (col >> 6) * CHUNK_ELEMS + r1l * A_LD + (col & 63);
    float bj0 = bhn[col], bj1 = bhn[col + 1];

    unsigned ph_empty = 0;
    unsigned ph_full  = 0;

    // ---- pre-loop prefetch (t=0): gi + hp
    float2 gr0, gz0, gn0, gr1, gz1, gn1;
    float2 hpA, hpB;
    if (wid < 8) {
        const float* gp0 = g_Gi + (long long)grow0 * G3H + col;
        const float* gp1 = g_Gi + (long long)grow1 * G3H + col;
        gr0 = __ldcs((const float2*)gp0);
        gz0 = __ldcs((const float2*)(gp0 + H_));
        gn0 = __ldcs((const float2*)(gp0 + 2 * H_));
        gr1 = __ldcs((const float2*)gp1);
        gz1 = __ldcs((const float2*)(gp1 + H_));
        gn1 = __ldcs((const float2*)(gp1 + 2 * H_));
        const __half* h0p = g_h[0] + rg * HGRP_ELEMS;
        unsigned hh0 = *(const unsigned*)(h0p + hb0);
        unsigned hh1 = *(const unsigned*)(h0p + hb1);
        hpA = __half22float2(*reinterpret_cast<__half2*>(&hh0));
        hpB = __half22float2(*reinterpret_cast<__half2*>(&hh1));
    }

    for (int t = 0; t < T_; t++) {
        if (wid == 8) {
            if (lid == 0) {
                const char* src = (const char*)(g_h[t & 1] + rg * HGRP_ELEMS);
                for (int kc = 0; kc < NCHUNK; kc++) {
                    int buf = kc & (NRING - 1);
                    mbar_wait(mb_empty + buf * 8, (ph_empty >> buf) & 1u);
                    ph_empty ^= 1u << buf;
                    mbar_expect_tx(mb_full + buf * 8, CHUNK_BYTES);
                    bulk_ld(sA_u32 + buf * CHUNK_BYTES,
                            src + (long long)kc * CHUNK_BYTES,
                            CHUNK_BYTES, mb_full + buf * 8);
                }
            }
        } else {
            bool rstA = (t + 1 < T_) ? get_reset_m(resets, (t + 1) * B_ + grow0, rmode) : false;
            bool rstB = (t + 1 < T_) ? get_reset_m(resets, (t + 1) * B_ + grow1, rmode) : false;

            // ---- mainloop: 16 chunks, 6 chains (3 gates x kk parity)
            float acc[6][4];
            #pragma unroll
            for (int i = 0; i < 6; i++)
                #pragma unroll
                for (int q = 0; q < 4; q++) acc[i][q] = 0.0f;

            for (int kc = 0; kc < NCHUNK; kc++) {
                const int buf = kc & (NRING - 1);
                mbar_wait(mb_full + buf * 8, (ph_full >> buf) & 1u);
                ph_full ^= 1u << buf;

                const unsigned aB = sA_u32 + buf * CHUNK_BYTES;
                #pragma unroll
                for (int kk = 0; kk < 4; kk++) {
                    unsigned ah[4];
                    ldsm_x4(ah, aB + a_off + kk * 32);
                    unsigned bbase = sW_u32 + b_half +
                                     (unsigned)(kc * 64 + kk * 16) * 48u + b_lane;
                    #pragma unroll
                    for (int tn = 0; tn < 3; tn++) {
                        unsigned bh[2];
                        ldsm_x2t(bh, bbase + tn * 16);
                        mma16816h(acc[tn * 2 + (kk & 1)], ah, bh);
                    }
                }
                if (lid == 0) mbar_arrive(mb_empty + buf * 8);
            }

            float gh[3][4];
            #pragma unroll
            for (int tn = 0; tn < 3; tn++)
                #pragma unroll
                for (int q = 0; q < 4; q++)
                    gh[tn][q] = acc[tn * 2][q] + acc[tn * 2 + 1][q];

            // ---- epilogue (fully register-local; hp carried from prev step)
            float hA0, hA1, hB0, hB1;
            {
                float r = 1.f / (1.f + __expf(-(gr0.x + gh[0][0])));
                float z = 1.f / (1.f + __expf(-(gz0.x + gh[1][0])));
                float n = tanhf(gn0.x + r * (gh[2][0] + bj0));
                hA0 = (1.f - z) * n + z * hpA.x;
            }
            {
                float r = 1.f / (1.f + __expf(-(gr0.y + gh[0][1])));
                float z = 1.f / (1.f + __expf(-(gz0.y + gh[1][1])));
                float n = tanhf(gn0.y + r * (gh[2][1] + bj1));
                hA1 = (1.f - z) * n + z * hpA.y;
            }
            {
                float r = 1.f / (1.f + __expf(-(gr1.x + gh[0][2])));
                float z = 1.f / (1.f + __expf(-(gz1.x + gh[1][2])));
                float n = tanhf(gn1.x + r * (gh[2][2] + bj0));
                hB0 = (1.f - z) * n + z * hpB.x;
            }
            {
                float r = 1.f / (1.f + __expf(-(gr1.y + gh[0][3])));
                float z = 1.f / (1.f + __expf(-(gz1.y + gh[1][3])));
                float n = tanhf(gn1.y + r * (gh[2][3] + bj1));
                hB1 = (1.f - z) * n + z * hpB.y;
            }

            float* outp = out + (long long)t * B_ * H_;
            *(float2*)(outp + (long long)grow0 * H_ + col) = make_float2(hA0, hA1);
            *(float2*)(outp + (long long)grow1 * H_ + col) = make_float2(hB0, hB1);

            if (t + 1 < T_) {
                __half* hdst = g_h[(t + 1) & 1] + rg * HGRP_ELEMS;
                float mA0 = rstA ? 0.f : hA0, mA1 = rstA ? 0.f : hA1;
                float mB0 = rstB ? 0.f : hB0, mB1 = rstB ? 0.f : hB1;
                __half2 sv0 = __floats2half2_rn(mA0, mA1);
                __half2 sv1 = __floats2half2_rn(mB0, mB1);
                *(unsigned*)(hdst + hb0) = *reinterpret_cast<unsigned*>(&sv0);
                *(unsigned*)(hdst + hb1) = *reinterpret_cast<unsigned*>(&sv1);
                // carry hp for next step (must equal the fp16-stored value)
                hpA = __half22float2(sv0);
                hpB = __half22float2(sv1);

                // prefetch gi for t+1 (h-independent): hides under the barrier
                const float* gp0 = g_Gi + (long long)(t + 1) * B_ * G3H
                                 + (long long)grow0 * G3H + col;
                const float* gp1 = g_Gi + (long long)(t + 1) * B_ * G3H
                                 + (long long)grow1 * G3H + col;
                gr0 = __ldcs((const float2*)gp0);
                gz0 = __ldcs((const float2*)(gp0 + H_));
                gn0 = __ldcs((const float2*)(gp0 + 2 * H_));
                gr1 = __ldcs((const float2*)gp1);
                gz1 = __ldcs((const float2*)(gp1 + H_));
                gn1 = __ldcs((const float2*)(gp1 + 2 * H_));
            }
        }

        // ---- grid barrier (proven)
        __threadfence();
        __syncthreads();
        if (tid == 0) {
            atomicAdd(&g_bar, 1u);
            unsigned target = (unsigned)gridDim.x * (unsigned)(t + 1);
            unsigned v;
            do {
                asm volatile("ld.acquire.gpu.u32 %0, [%1];" : "=r"(v) : "l"(&g_bar));
                if (v < target) __nanosleep(32);
            } while (v < target);
        }
        __syncthreads();
    }
}

// ---------------------------------------------------------------------------
extern "C" void kernel_launch(void* const* d_in, const int* in_sizes, int n_in,
                              void* d_out, int out_size)
{
    const float* x      = (const float*)d_in[0];
    const void*  resets = d_in[1];
    const float* h0     = (const float*)d_in[2];
    const float* Wi     = (const float*)d_in[3];
    const float* bi     = (const float*)d_in[4];
    const float* Wh     = (const float*)d_in[5];
    const float* bhn    = (const float*)d_in[6];
    float* out = (float*)d_out;

    cudaFuncSetAttribute(scan_kernel, cudaFuncAttributeMaxDynamicSharedMemorySize,
                         SMEM_TOTAL);

    init_kernel<<<1, 1>>>((const unsigned char*)resets);
    prep_h_kernel<<<(B_ * H_) / 256, 256>>>(h0, resets);
    gi_gemm_kernel<<<dim3(G3H / NT, (T_ * B_) / MT), 256>>>(x, Wi, bi);
    scan_kernel<<<NCTA, NTHREADS, SMEM_TOTAL>>>(Wh, bhn, resets, out);
}

// round 14
// speedup vs baseline: 2.2783x; 1.0492x over previous
#include <cuda_runtime.h>
#include <cuda_bf16.h>
#include <cuda_fp16.h>
#include <mma.h>
#include <cstdint>

using namespace nvcuda;

#define T_   512
#define B_   128
#define D_   512
#define H_   1024
#define G3H  3072

// ---- gi_gemm tiling (proven fp16 single-plane) ----
#define MT   128
#define NT   64
#define KT   32
#define PADA 40
#define PADB 72

// ---- scan: 2 row-groups x 64 col-groups; CTA = [64 rows x 16 cols], fp16 ----
#define NCTA    128
#define RROWS   64
#define SKT     64
#define NCHUNK  (H_ / SKT)                  // 16
#define NRING   4
#define A_LD    72                          // fp16 elems/row (144B, conflict-free)
#define CHUNK_ELEMS (RROWS * A_LD)          // 4608
#define CHUNK_BYTES (CHUNK_ELEMS * 2)       // 9216
#define HGRP_ELEMS (NCHUNK * CHUNK_ELEMS)
#define B_LD    24
#define BHALF_BYTES (H_ * B_LD * 2)         // 49152
#define SM_W    0
#define SM_A    (2 * BHALF_BYTES)           // 98304
#define SM_CTL  (SM_A + NRING * CHUNK_BYTES) // 135168
#define SMEM_TOTAL (SM_CTL + 64)
#define NTHREADS 288

__device__ __align__(256) float  g_Gi[(long long)T_ * B_ * G3H];
// h scratch: [pingpong][rowgroup][chunk][64][72] fp16
__device__ __align__(256) __half g_h[2][2 * HGRP_ELEMS];
__device__ int      g_reset_mode;
__device__ unsigned g_bar;

// ---------------------------------------------------------------------------
__global__ void init_kernel(const unsigned char* __restrict__ resets) {
    const unsigned int* w = (const unsigned int*)resets;
    bool i32 = true, f32 = true;
    for (int i = 0; i < 16; i++) {
        unsigned int v = w[i];
        if (v != 0u && v != 1u) i32 = false;
        if (v != 0u && v != 0x3F800000u) f32 = false;
    }
    g_reset_mode = i32 ? 1 : (f32 ? 2 : 0);
    g_bar = 0u;
}

__device__ __forceinline__ bool get_reset_m(const void* r, int idx, int m) {
    if (m == 1) return ((const int*)r)[idx] != 0;
    if (m == 2) return ((const float*)r)[idx] != 0.0f;
    return ((const unsigned char*)r)[idx] != 0;
}

__device__ __forceinline__ unsigned smem_u32(const void* p) {
    return (unsigned)__cvta_generic_to_shared(p);
}
__device__ __forceinline__ void mbar_init(unsigned a, unsigned c) {
    asm volatile("mbarrier.init.shared.b64 [%0], %1;" :: "r"(a), "r"(c) : "memory");
}
__device__ __forceinline__ void mbar_arrive(unsigned a) {
    asm volatile("mbarrier.arrive.shared.b64 _, [%0];" :: "r"(a) : "memory");
}
__device__ __forceinline__ void mbar_expect_tx(unsigned a, unsigned bytes) {
    asm volatile("mbarrier.arrive.expect_tx.shared.b64 _, [%0], %1;"
                 :: "r"(a), "r"(bytes) : "memory");
}
__device__ __forceinline__ void mbar_wait(unsigned a, unsigned parity) {
    asm volatile(
        "{\n\t.reg .pred P;\n\t"
        "W_%=:\n\t"
        "mbarrier.try_wait.parity.acquire.cta.shared::cta.b64 P, [%0], %1, 0x989680;\n\t"
        "@P bra D_%=;\n\t"
        "bra.uni W_%=;\n\t"
        "D_%=:\n\t}"
        :: "r"(a), "r"(parity) : "memory");
}
__device__ __forceinline__ void bulk_ld(unsigned dst, const void* src,
                                        unsigned bytes, unsigned mbar) {
    asm volatile(
        "cp.async.bulk.shared::cta.global.mbarrier::complete_tx::bytes [%0], [%1], %2, [%3];"
        :: "r"(dst), "l"(src), "r"(bytes), "r"(mbar) : "memory");
}
__device__ __forceinline__ unsigned ld_acquire(const unsigned* p) {
    unsigned v;
    asm volatile("ld.acquire.gpu.u32 %0, [%1];" : "=r"(v) : "l"(p) : "memory");
    return v;
}

__device__ __forceinline__ void ldsm_x4(unsigned* r, unsigned a) {
    asm volatile("ldmatrix.sync.aligned.m8n8.x4.shared.b16 {%0,%1,%2,%3}, [%4];"
                 : "=r"(r[0]), "=r"(r[1]), "=r"(r[2]), "=r"(r[3]) : "r"(a));
}
__device__ __forceinline__ void ldsm_x2t(unsigned* r, unsigned a) {
    asm volatile("ldmatrix.sync.aligned.m8n8.x2.trans.shared.b16 {%0,%1}, [%2];"
                 : "=r"(r[0]), "=r"(r[1]) : "r"(a));
}
__device__ __forceinline__ void mma16816h(float* c, const unsigned* a, const unsigned* b) {
    asm volatile(
        "mma.sync.aligned.m16n8k16.row.col.f32.f16.f16.f32 "
        "{%0,%1,%2,%3}, {%4,%5,%6,%7}, {%8,%9}, {%0,%1,%2,%3};"
        : "+f"(c[0]), "+f"(c[1]), "+f"(c[2]), "+f"(c[3])
        : "r"(a[0]), "r"(a[1]), "r"(a[2]), "r"(a[3]), "r"(b[0]), "r"(b[1]));
}

__global__ void prep_h_kernel(const float* __restrict__ h0,
                              const void* __restrict__ resets)
{
    int i = blockIdx.x * 256 + threadIdx.x;    // 0 .. B*H-1
    int b = i >> 10;
    int k = i & 1023;
    float v = get_reset_m(resets, b, g_reset_mode) ? 0.0f : h0[i];
    int rg = b >> 6;
    int r  = b & 63;
    int o = rg * HGRP_ELEMS + (k >> 6) * CHUNK_ELEMS + r * A_LD + (k & 63);
    g_h[0][o] = __float2half_rn(v);
}

// ---------------------------------------------------------------------------
// Phase B: Gi = X @ Wi + bi   (proven, fp16 single-plane, verbatim)
// ---------------------------------------------------------------------------
__global__ __launch_bounds__(256) void gi_gemm_kernel(
    const float* __restrict__ X,
    const float* __restrict__ Wi,
    const float* __restrict__ bi)
{
    __shared__ __align__(16) __half sA[MT * PADA];
    __shared__ __align__(16) __half sB[KT * PADB];
    __shared__ __align__(16) float sBias[16 * NT];

    const int n0  = blockIdx.x * NT;
    const long long m0 = (long long)blockIdx.y * MT;
    const int tid  = threadIdx.x;
    const int warp = tid >> 5;
    const int wm   = warp & 3;
    const int wn   = warp >> 2;

    for (int i = tid; i < 16 * NT; i += 256) sBias[i] = bi[n0 + (i % NT)];
    __syncthreads();

    wmma::fragment<wmma::accumulator, 16, 16, 16, float> acc[2][2];
    for (int i = 0; i < 2; i++)
        for (int j = 0; j < 2; j++)
            wmma::load_matrix_sync(acc[i][j], &sBias[wn * 32 + j * 16], NT,
                                   wmma::mem_row_major);

    for (int k0 = 0; k0 < D_; k0 += KT) {
        __syncthreads();
        for (int i = tid; i < MT * KT / 4; i += 256) {
            int r = i >> 3;
            int c = (i & 7) * 4;
            float4 v = *(const float4*)(X + (m0 + r) * D_ + k0 + c);
            sA[r * PADA + c + 0] = __float2half_rn(v.x);
            sA[r * PADA + c + 1] = __float2half_rn(v.y);
            sA[r * PADA + c + 2] = __float2half_rn(v.z);
            sA[r * PADA + c + 3] = __float2half_rn(v.w);
        }
        for (int i = tid; i < KT * NT / 4; i += 256) {
            int r = i >> 4;
            int c = (i & 15) * 4;
            float4 v = *(const float4*)(Wi + (long long)(k0 + r) * G3H + n0 + c);
            sB[r * PADB + c + 0] = __float2half_rn(v.x);
            sB[r * PADB + c + 1] = __float2half_rn(v.y);
            sB[r * PADB + c + 2] = __float2half_rn(v.z);
            sB[r * PADB + c + 3] = __float2half_rn(v.w);
        }
        __syncthreads();

        #pragma unroll
        for (int kk = 0; kk < KT; kk += 16) {
            wmma::fragment<wmma::matrix_a, 16, 16, 16, __half, wmma::row_major> a[2];
            wmma::fragment<wmma::matrix_b, 16, 16, 16, __half, wmma::row_major> b[2];
            #pragma unroll
            for (int i = 0; i < 2; i++)
                wmma::load_matrix_sync(a[i], &sA[(wm * 32 + i * 16) * PADA + kk], PADA);
            #pragma unroll
            for (int j = 0; j < 2; j++)
                wmma::load_matrix_sync(b[j], &sB[kk * PADB + wn * 32 + j * 16], PADB);
            #pragma unroll
            for (int i = 0; i < 2; i++)
                #pragma unroll
                for (int j = 0; j < 2; j++)
                    wmma::mma_sync(acc[i][j], a[i], b[j], acc[i][j]);
        }
    }

    for (int i = 0; i < 2; i++)
        for (int j = 0; j < 2; j++) {
            float* p = g_Gi + (m0 + wm * 32 + i * 16) * G3H + n0 + wn * 32 + j * 16;
            wmma::store_matrix_sync(p, acc[i][j], G3H, wmma::mem_row_major);
        }
}

// ---------------------------------------------------------------------------
// Persistent scan (fp16x1, SKT=64): 128 CTAs x 288 threads.
// NEW: producer-only epoch wait. Consumers: epilogue -> hdst store -> fence ->
// bar.sync(consumers) -> tid0 arrive -> out store + gi prefetch -> next step
// (gated transitively via mb_full). Producer: waits g_bar >= 128*t before
// issuing step t's TMA loads.
// ---------------------------------------------------------------------------
__global__ __launch_bounds__(NTHREADS, 1) void scan_kernel(
    const float* __restrict__ Wh,
    const float* __restrict__ bhn,
    const void*  __restrict__ resets,
    float*       __restrict__ out)
{
    extern __shared__ __align__(128) char sm[];
    __half* sW = (__half*)(sm + SM_W);
    const unsigned sW_u32 = smem_u32(sm + SM_W);
    const unsigned sA_u32 = smem_u32(sm + SM_A);
    const unsigned ctl      = smem_u32(sm + SM_CTL);
    const unsigned mb_full  = ctl;        // 4 x 8B
    const unsigned mb_empty = ctl + 32;   // 4 x 8B

    const int tid = threadIdx.x;
    const int wid = tid >> 5;
    const int lid = tid & 31;
    const int bid = blockIdx.x;
    const int rg  = bid >> 6;
    const int j0  = (bid & 63) * 16;
    const int rmode = g_reset_mode;

    // ---- load resident Wh slice: 48 packed cols (fp16)
    for (int idx = tid; idx < H_ * 48; idx += NTHREADS) {
        int k = idx / 48;
        int c = idx - k * 48;
        int h = c >= 24;
        int cr = c - h * 24;
        int g  = cr >> 3;
        int cj = cr & 7;
        float v = Wh[(long long)k * G3H + g * H_ + j0 + h * 8 + cj];
        sW[h * (H_ * B_LD) + k * B_LD + cr] = __float2half_rn(v);
    }

    if (tid == 0) {
        #pragma unroll
        for (int i = 0; i < NRING; i++) {
            mbar_init(mb_full + i * 8, 1);
            mbar_init(mb_empty + i * 8, 8);
        }
    }
    __syncthreads();
    if (tid < 8) {
        #pragma unroll
        for (int i = 0; i < NRING; i++) mbar_arrive(mb_empty + i * 8);
    }
    asm volatile("fence.proxy.async;" ::: "memory");
    __syncthreads();

    // consumer geometry
    const int wm = wid & 3;
    const int nh = (wid >> 2) & 1;
    const unsigned a_off = (unsigned)((wm * 16 + (lid & 15)) * 144 + (lid >> 4) * 16);
    const unsigned b_half = (unsigned)(nh * BHALF_BYTES);
    const unsigned b_lane = (unsigned)((lid & 15) * 48);

    // epilogue coords
    const int r0l = wm * 16 + (lid >> 2);
    const int r1l = r0l + 8;
    const int grow0 = rg * 64 + r0l;
    const int grow1 = rg * 64 + r1l;
    const int col = j0 + nh * 8 + (lid & 3) * 2;
    const int hb0 = (col >> 6) * CHUNK_ELEMS + r0l * A_LD + (col & 63);
    const int hb1 = (col >> 6) * CHUNK_ELEMS + r1l * A_LD + (col & 63);
    float bj0 = bhn[col], bj1 = bhn[col + 1];

    unsigned ph_empty = 0;
    unsigned ph_full  = 0;

    // ---- pre-loop prefetch (t=0): gi + hp
    float2 gr0, gz0, gn0, gr1, gz1, gn1;
    float2 hpA, hpB;
    if (wid < 8) {
        const float* gp0 = g_Gi + (long long)grow0 * G3H + col;
        const float* gp1 = g_Gi + (long long)grow1 * G3H + col;
        gr0 = __ldcs((const float2*)gp0);
        gz0 = __ldcs((const float2*)(gp0 + H_));
        gn0 = __ldcs((const float2*)(gp0 + 2 * H_));
        gr1 = __ldcs((const float2*)gp1);
        gz1 = __ldcs((const float2*)(gp1 + H_));
        gn1 = __ldcs((const float2*)(gp1 + 2 * H_));
        const __half* h0p = g_h[0] + rg * HGRP_ELEMS;
        unsigned hh0 = *(const unsigned*)(h0p + hb0);
        unsigned hh1 = *(const unsigned*)(h0p + hb1);
        hpA = __half22float2(*reinterpret_cast<__half2*>(&hh0));
        hpB = __half22float2(*reinterpret_cast<__half2*>(&hh1));
    }

    for (int t = 0; t < T_; t++) {
        if (wid == 8) {
            if (lid == 0) {
                // epoch gate: all CTAs must have finished step t-1 epilogues
                if (t > 0) {
                    const unsigned target = (unsigned)NCTA * (unsigned)t;
                    while (ld_acquire(&g_bar) < target) { }
                }
                const char* src = (const char*)(g_h[t & 1] + rg * HGRP_ELEMS);
                for (int kc = 0; kc < NCHUNK; kc++) {
                    int buf = kc & (NRING - 1);
                    mbar_wait(mb_empty + buf * 8, (ph_empty >> buf) & 1u);
                    ph_empty ^= 1u << buf;
                    mbar_expect_tx(mb_full + buf * 8, CHUNK_BYTES);
                    bulk_ld(sA_u32 + buf * CHUNK_BYTES,
                            src + (long long)kc * CHUNK_BYTES,
                            CHUNK_BYTES, mb_full + buf * 8);
                }
            }
        } else {
            bool rstA = (t + 1 < T_) ? get_reset_m(resets, (t + 1) * B_ + grow0, rmode) : false;
            bool rstB = (t + 1 < T_) ? get_reset_m(resets, (t + 1) * B_ + grow1, rmode) : false;

            // ---- mainloop: 16 chunks, 6 chains (3 gates x kk parity)
            float acc[6][4];
            #pragma unroll
            for (int i = 0; i < 6; i++)
                #pragma unroll
                for (int q = 0; q < 4; q++) acc[i][q] = 0.0f;

            for (int kc = 0; kc < NCHUNK; kc++) {
                const int buf = kc & (NRING - 1);
                mbar_wait(mb_full + buf * 8, (ph_full >> buf) & 1u);
                ph_full ^= 1u << buf;

                const unsigned aB = sA_u32 + buf * CHUNK_BYTES;
                #pragma unroll
                for (int kk = 0; kk < 4; kk++) {
                    unsigned ah[4];
                    ldsm_x4(ah, aB + a_off + kk * 32);
                    unsigned bbase = sW_u32 + b_half +
                                     (unsigned)(kc * 64 + kk * 16) * 48u + b_lane;
                    #pragma unroll
                    for (int tn = 0; tn < 3; tn++) {
                        unsigned bh[2];
                        ldsm_x2t(bh, bbase + tn * 16);
                        mma16816h(acc[tn * 2 + (kk & 1)], ah, bh);
                    }
                }
                if (lid == 0) mbar_arrive(mb_empty + buf * 8);
            }

            float gh[3][4];
            #pragma unroll
            for (int tn = 0; tn < 3; tn++)
                #pragma unroll
                for (int q = 0; q < 4; q++)
                    gh[tn][q] = acc[tn * 2][q] + acc[tn * 2 + 1][q];

            // ---- epilogue (register-local; hp carried)
            float hA0, hA1, hB0, hB1;
            {
                float r = 1.f / (1.f + __expf(-(gr0.x + gh[0][0])));
                float z = 1.f / (1.f + __expf(-(gz0.x + gh[1][0])));
                float n = tanhf(gn0.x + r * (gh[2][0] + bj0));
                hA0 = (1.f - z) * n + z * hpA.x;
            }
            {
                float r = 1.f / (1.f + __expf(-(gr0.y + gh[0][1])));
                float z = 1.f / (1.f + __expf(-(gz0.y + gh[1][1])));
                float n = tanhf(gn0.y + r * (gh[2][1] + bj1));
                hA1 = (1.f - z) * n + z * hpA.y;
            }
            {
                float r = 1.f / (1.f + __expf(-(gr1.x + gh[0][2])));
                float z = 1.f / (1.f + __expf(-(gz1.x + gh[1][2])));
                float n = tanhf(gn1.x + r * (gh[2][2] + bj0));
                hB0 = (1.f - z) * n + z * hpB.x;
            }
            {
                float r = 1.f / (1.f + __expf(-(gr1.y + gh[0][3])));
                float z = 1.f / (1.f + __expf(-(gz1.y + gh[1][3])));
                float n = tanhf(gn1.y + r * (gh[2][3] + bj1));
                hB1 = (1.f - z) * n + z * hpB.y;
            }

            if (t + 1 < T_) {
                // masked h store FIRST (this is what the epoch release covers)
                __half* hdst = g_h[(t + 1) & 1] + rg * HGRP_ELEMS;
                float mA0 = rstA ? 0.f : hA0, mA1 = rstA ? 0.f : hA1;
                float mB0 = rstB ? 0.f : hB0, mB1 = rstB ? 0.f : hB1;
                __half2 sv0 = __floats2half2_rn(mA0, mA1);
                __half2 sv1 = __floats2half2_rn(mB0, mB1);
                *(unsigned*)(hdst + hb0) = *reinterpret_cast<unsigned*>(&sv0);
                *(unsigned*)(hdst + hb1) = *reinterpret_cast<unsigned*>(&sv1);
                hpA = __half22float2(sv0);
                hpB = __half22float2(sv1);

                // release: fence each writer, consumer-warps barrier, one arrive
                __threadfence();
                asm volatile("bar.sync 1, 256;" ::: "memory");
                if (tid == 0) atomicAdd(&g_bar, 1u);
            }

            // out store + next-step gi prefetch: hidden under the TMA refill
            float* outp = out + (long long)t * B_ * H_;
            *(float2*)(outp + (long long)grow0 * H_ + col) = make_float2(hA0, hA1);
            *(float2*)(outp + (long long)grow1 * H_ + col) = make_float2(hB0, hB1);

            if (t + 1 < T_) {
                const float* gp0 = g_Gi + (long long)(t + 1) * B_ * G3H
                                 + (long long)grow0 * G3H + col;
                const float* gp1 = g_Gi + (long long)(t + 1) * B_ * G3H
                                 + (long long)grow1 * G3H + col;
                gr0 = __ldcs((const float2*)gp0);
                gz0 = __ldcs((const float2*)(gp0 + H_));
                gn0 = __ldcs((const float2*)(gp0 + 2 * H_));
                gr1 = __ldcs((const float2*)gp1);
                gz1 = __ldcs((const float2*)(gp1 + H_));
                gn1 = __ldcs((const float2*)(gp1 + 2 * H_));
            }
        }
        // no CTA-wide or grid-wide barrier here: producer gates via epoch,
        // consumers gate via mb_full.
    }
}

// ---------------------------------------------------------------------------
extern "C" void kernel_launch(void* const* d_in, const int* in_sizes, int n_in,
                              void* d_out, int out_size)
{
    const float* x      = (const float*)d_in[0];
    const void*  resets = d_in[1];
    const float* h0     = (const float*)d_in[2];
    const float* Wi     = (const float*)d_in[3];
    const float* bi     = (const float*)d_in[4];
    const float* Wh     = (const float*)d_in[5];
    const float* bhn    = (const float*)d_in[6];
    float* out = (float*)d_out;

    cudaFuncSetAttribute(scan_kernel, cudaFuncAttributeMaxDynamicSharedMemorySize,
                         SMEM_TOTAL);

    init_kernel<<<1, 1>>>((const unsigned char*)resets);
    prep_h_kernel<<<(B_ * H_) / 256, 256>>>(h0, resets);
    gi_gemm_kernel<<<dim3(G3H / NT, (T_ * B_) / MT), 256>>>(x, Wi, bi);
    scan_kernel<<<NCTA, NTHREADS, SMEM_TOTAL>>>(Wh, bhn, resets, out);
}

// round 15
// speedup vs baseline: 2.2973x; 1.0083x over previous
#include <cuda_runtime.h>
#include <cuda_bf16.h>
#include <cuda_fp16.h>
#include <mma.h>
#include <cstdint>

using namespace nvcuda;

#define T_   512
#define B_   128
#define D_   512
#define H_   1024
#define G3H  3072

// ---- gi_gemm tiling (proven fp16 single-plane) ----
#define MT   128
#define NT   64
#define KT   32
#define PADA 40
#define PADB 72

// ---- scan: 2 row-groups x 64 col-groups; CTA = [64 rows x 16 cols], fp16 ----
#define NCTA    128
#define RROWS   64
#define SKT     128
#define NCHUNK  (H_ / SKT)                  // 8
#define NRING   4
#define A_LD    136                         // fp16 elems/row (272B, conflict-free)
#define CHUNK_ELEMS (RROWS * A_LD)          // 8704
#define CHUNK_BYTES (CHUNK_ELEMS * 2)       // 17408
#define HGRP_ELEMS (NCHUNK * CHUNK_ELEMS)
#define B_LD    24
#define BHALF_BYTES (H_ * B_LD * 2)         // 49152
#define SM_W    0
#define SM_A    (2 * BHALF_BYTES)           // 98304
#define SM_CTL  (SM_A + NRING * CHUNK_BYTES) // 167936
#define SMEM_TOTAL (SM_CTL + 64)
#define NTHREADS 288

__device__ __align__(256) float  g_Gi[(long long)T_ * B_ * G3H];
// h scratch: [pingpong][rowgroup][chunk][64][136] fp16
__device__ __align__(256) __half g_h[2][2 * HGRP_ELEMS];
__device__ int      g_reset_mode;
__device__ unsigned g_bar;

// ---------------------------------------------------------------------------
__global__ void init_kernel(const unsigned char* __restrict__ resets) {
    const unsigned int* w = (const unsigned int*)resets;
    bool i32 = true, f32 = true;
    for (int i = 0; i < 16; i++) {
        unsigned int v = w[i];
        if (v != 0u && v != 1u) i32 = false;
        if (v != 0u && v != 0x3F800000u) f32 = false;
    }
    g_reset_mode = i32 ? 1 : (f32 ? 2 : 0);
    g_bar = 0u;
}

__device__ __forceinline__ bool get_reset_m(const void* r, int idx, int m) {
    if (m == 1) return ((const int*)r)[idx] != 0;
    if (m == 2) return ((const float*)r)[idx] != 0.0f;
    return ((const unsigned char*)r)[idx] != 0;
}

__device__ __forceinline__ unsigned smem_u32(const void* p) {
    return (unsigned)__cvta_generic_to_shared(p);
}
__device__ __forceinline__ void mbar_init(unsigned a, unsigned c) {
    asm volatile("mbarrier.init.shared.b64 [%0], %1;" :: "r"(a), "r"(c) : "memory");
}
__device__ __forceinline__ void mbar_arrive(unsigned a) {
    asm volatile("mbarrier.arrive.shared.b64 _, [%0];" :: "r"(a) : "memory");
}
__device__ __forceinline__ void mbar_expect_tx(unsigned a, unsigned bytes) {
    asm volatile("mbarrier.arrive.expect_tx.shared.b64 _, [%0], %1;"
                 :: "r"(a), "r"(bytes) : "memory");
}
__device__ __forceinline__ void mbar_wait(unsigned a, unsigned parity) {
    asm volatile(
        "{\n\t.reg .pred P;\n\t"
        "W_%=:\n\t"
        "mbarrier.try_wait.parity.acquire.cta.shared::cta.b64 P, [%0], %1, 0x989680;\n\t"
        "@P bra D_%=;\n\t"
        "bra.uni W_%=;\n\t"
        "D_%=:\n\t}"
        :: "r"(a), "r"(parity) : "memory");
}
__device__ __forceinline__ void bulk_ld(unsigned dst, const void* src,
                                        unsigned bytes, unsigned mbar) {
    asm volatile(
        "cp.async.bulk.shared::cta.global.mbarrier::complete_tx::bytes [%0], [%1], %2, [%3];"
        :: "r"(dst), "l"(src), "r"(bytes), "r"(mbar) : "memory");
}
__device__ __forceinline__ unsigned ld_acquire(const unsigned* p) {
    unsigned v;
    asm volatile("ld.acquire.gpu.u32 %0, [%1];" : "=r"(v) : "l"(p) : "memory");
    return v;
}

__device__ __forceinline__ void ldsm_x4(unsigned* r, unsigned a) {
    asm volatile("ldmatrix.sync.aligned.m8n8.x4.shared.b16 {%0,%1,%2,%3}, [%4];"
                 : "=r"(r[0]), "=r"(r[1]), "=r"(r[2]), "=r"(r[3]) : "r"(a));
}
__device__ __forceinline__ void ldsm_x4t(unsigned* r, unsigned a) {
    asm volatile("ldmatrix.sync.aligned.m8n8.x4.trans.shared.b16 {%0,%1,%2,%3}, [%4];"
                 : "=r"(r[0]), "=r"(r[1]), "=r"(r[2]), "=r"(r[3]) : "r"(a));
}
__device__ __forceinline__ void ldsm_x2t(unsigned* r, unsigned a) {
    asm volatile("ldmatrix.sync.aligned.m8n8.x2.trans.shared.b16 {%0,%1}, [%2];"
                 : "=r"(r[0]), "=r"(r[1]) : "r"(a));
}
__device__ __forceinline__ void mma16816h(float* c, const unsigned* a, const unsigned* b) {
    asm volatile(
        "mma.sync.aligned.m16n8k16.row.col.f32.f16.f16.f32 "
        "{%0,%1,%2,%3}, {%4,%5,%6,%7}, {%8,%9}, {%0,%1,%2,%3};"
        : "+f"(c[0]), "+f"(c[1]), "+f"(c[2]), "+f"(c[3])
        : "r"(a[0]), "r"(a[1]), "r"(a[2]), "r"(a[3]), "r"(b[0]), "r"(b[1]));
}

__global__ void prep_h_kernel(const float* __restrict__ h0,
                              const void* __restrict__ resets)
{
    int i = blockIdx.x * 256 + threadIdx.x;    // 0 .. B*H-1
    int b = i >> 10;
    int k = i & 1023;
    float v = get_reset_m(resets, b, g_reset_mode) ? 0.0f : h0[i];
    int rg = b >> 6;
    int r  = b & 63;
    int o = rg * HGRP_ELEMS + (k >> 7) * CHUNK_ELEMS + r * A_LD + (k & 127);
    g_h[0][o] = __float2half_rn(v);
}

// ---------------------------------------------------------------------------
// Phase B: Gi = X @ Wi + bi   (proven, fp16 single-plane, verbatim)
// ---------------------------------------------------------------------------
__global__ __launch_bounds__(256) void gi_gemm_kernel(
    const float* __restrict__ X,
    const float* __restrict__ Wi,
    const float* __restrict__ bi)
{
    __shared__ __align__(16) __half sA[MT * PADA];
    __shared__ __align__(16) __half sB[KT * PADB];
    __shared__ __align__(16) float sBias[16 * NT];

    const int n0  = blockIdx.x * NT;
    const long long m0 = (long long)blockIdx.y * MT;
    const int tid  = threadIdx.x;
    const int warp = tid >> 5;
    const int wm   = warp & 3;
    const int wn   = warp >> 2;

    for (int i = tid; i < 16 * NT; i += 256) sBias[i] = bi[n0 + (i % NT)];
    __syncthreads();

    wmma::fragment<wmma::accumulator, 16, 16, 16, float> acc[2][2];
    for (int i = 0; i < 2; i++)
        for (int j = 0; j < 2; j++)
            wmma::load_matrix_sync(acc[i][j], &sBias[wn * 32 + j * 16], NT,
                                   wmma::mem_row_major);

    for (int k0 = 0; k0 < D_; k0 += KT) {
        __syncthreads();
        for (int i = tid; i < MT * KT / 4; i += 256) {
            int r = i >> 3;
            int c = (i & 7) * 4;
            float4 v = *(const float4*)(X + (m0 + r) * D_ + k0 + c);
            sA[r * PADA + c + 0] = __float2half_rn(v.x);
            sA[r * PADA + c + 1] = __float2half_rn(v.y);
            sA[r * PADA + c + 2] = __float2half_rn(v.z);
            sA[r * PADA + c + 3] = __float2half_rn(v.w);
        }
        for (int i = tid; i < KT * NT / 4; i += 256) {
            int r = i >> 4;
            int c = (i & 15) * 4;
            float4 v = *(const float4*)(Wi + (long long)(k0 + r) * G3H + n0 + c);
            sB[r * PADB + c + 0] = __float2half_rn(v.x);
            sB[r * PADB + c + 1] = __float2half_rn(v.y);
            sB[r * PADB + c + 2] = __float2half_rn(v.z);
            sB[r * PADB + c + 3] = __float2half_rn(v.w);
        }
        __syncthreads();

        #pragma unroll
        for (int kk = 0; kk < KT; kk += 16) {
            wmma::fragment<wmma::matrix_a, 16, 16, 16, __half, wmma::row_major> a[2];
            wmma::fragment<wmma::matrix_b, 16, 16, 16, __half, wmma::row_major> b[2];
            #pragma unroll
            for (int i = 0; i < 2; i++)
                wmma::load_matrix_sync(a[i], &sA[(wm * 32 + i * 16) * PADA + kk], PADA);
            #pragma unroll
            for (int j = 0; j < 2; j++)
                wmma::load_matrix_sync(b[j], &sB[kk * PADB + wn * 32 + j * 16], PADB);
            #pragma unroll
            for (int i = 0; i < 2; i++)
                #pragma unroll
                for (int j = 0; j < 2; j++)
                    wmma::mma_sync(acc[i][j], a[i], b[j], acc[i][j]);
        }
    }

    for (int i = 0; i < 2; i++)
        for (int j = 0; j < 2; j++) {
            float* p = g_Gi + (m0 + wm * 32 + i * 16) * G3H + n0 + wn * 32 + j * 16;
            wmma::store_matrix_sync(p, acc[i][j], G3H, wmma::mem_row_major);
        }
}

// ---------------------------------------------------------------------------
// Persistent scan (fp16x1, SKT=128): 128 CTAs x 288 threads.
// Producer-only epoch wait (proven R14). B loads via x4.trans + x2.trans.
// ---------------------------------------------------------------------------
__global__ __launch_bounds__(NTHREADS, 1) void scan_kernel(
    const float* __restrict__ Wh,
    const float* __restrict__ bhn,
    const void*  __restrict__ resets,
    float*       __restrict__ out)
{
    extern __shared__ __align__(128) char sm[];
    __half* sW = (__half*)(sm + SM_W);
    const unsigned sW_u32 = smem_u32(sm + SM_W);
    const unsigned sA_u32 = smem_u32(sm + SM_A);
    const unsigned ctl      = smem_u32(sm + SM_CTL);
    const unsigned mb_full  = ctl;        // 4 x 8B
    const unsigned mb_empty = ctl + 32;   // 4 x 8B

    const int tid = threadIdx.x;
    const int wid = tid >> 5;
    const int lid = tid & 31;
    const int bid = blockIdx.x;
    const int rg  = bid >> 6;
    const int j0  = (bid & 63) * 16;
    const int rmode = g_reset_mode;

    // ---- load resident Wh slice: 48 packed cols (fp16)
    for (int idx = tid; idx < H_ * 48; idx += NTHREADS) {
        int k = idx / 48;
        int c = idx - k * 48;
        int h = c >= 24;
        int cr = c - h * 24;
        int g  = cr >> 3;
        int cj = cr & 7;
        float v = Wh[(long long)k * G3H + g * H_ + j0 + h * 8 + cj];
        sW[h * (H_ * B_LD) + k * B_LD + cr] = __float2half_rn(v);
    }

    if (tid == 0) {
        #pragma unroll
        for (int i = 0; i < NRING; i++) {
            mbar_init(mb_full + i * 8, 1);
            mbar_init(mb_empty + i * 8, 8);
        }
    }
    __syncthreads();
    if (tid < 8) {
        #pragma unroll
        for (int i = 0; i < NRING; i++) mbar_arrive(mb_empty + i * 8);
    }
    asm volatile("fence.proxy.async;" ::: "memory");
    __syncthreads();

    // consumer geometry (SKT=128: 272B A rows, kk 0..7)
    const int wm = wid & 3;
    const int nh = (wid >> 2) & 1;
    const unsigned a_off = (unsigned)((wm * 16 + (lid & 15)) * 272 + (lid >> 4) * 16);
    const unsigned b_half = (unsigned)(nh * BHALF_BYTES);
    const unsigned b_lane  = (unsigned)((lid & 15) * 48);              // x2t (lanes 0-15)
    const unsigned b_lane4 = (unsigned)(((lid >> 4) & 1) * 16 + (lid & 15) * 48); // x4t

    // epilogue coords
    const int r0l = wm * 16 + (lid >> 2);
    const int r1l = r0l + 8;
    const int grow0 = rg * 64 + r0l;
    const int grow1 = rg * 64 + r1l;
    const int col = j0 + nh * 8 + (lid & 3) * 2;
    const int hb0 = (col >> 7) * CHUNK_ELEMS + r0l * A_LD + (col & 127);
    const int hb1 = (col >> 7) * CHUNK_ELEMS + r1l * A_LD + (col & 127);
    float bj0 = bhn[col], bj1 = bhn[col + 1];

    unsigned ph_empty = 0;
    unsigned ph_full  = 0;

    // ---- pre-loop prefetch (t=0): gi + hp
    float2 gr0, gz0, gn0, gr1, gz1, gn1;
    float2 hpA, hpB;
    if (wid < 8) {
        const float* gp0 = g_Gi + (long long)grow0 * G3H + col;
        const float* gp1 = g_Gi + (long long)grow1 * G3H + col;
        gr0 = __ldcs((const float2*)gp0);
        gz0 = __ldcs((const float2*)(gp0 + H_));
        gn0 = __ldcs((const float2*)(gp0 + 2 * H_));
        gr1 = __ldcs((const float2*)gp1);
        gz1 = __ldcs((const float2*)(gp1 + H_));
        gn1 = __ldcs((const float2*)(gp1 + 2 * H_));
        const __half* h0p = g_h[0] + rg * HGRP_ELEMS;
        unsigned hh0 = *(const unsigned*)(h0p + hb0);
        unsigned hh1 = *(const unsigned*)(h0p + hb1);
        hpA = __half22float2(*reinterpret_cast<__half2*>(&hh0));
        hpB = __half22float2(*reinterpret_cast<__half2*>(&hh1));
    }

    for (int t = 0; t < T_; t++) {
        if (wid == 8) {
            if (lid == 0) {
                if (t > 0) {
                    const unsigned target = (unsigned)NCTA * (unsigned)t;
                    while (ld_acquire(&g_bar) < target) { }
                }
                const char* src = (const char*)(g_h[t & 1] + rg * HGRP_ELEMS);
                for (int kc = 0; kc < NCHUNK; kc++) {
                    int buf = kc & (NRING - 1);
                    mbar_wait(mb_empty + buf * 8, (ph_empty >> buf) & 1u);
                    ph_empty ^= 1u << buf;
                    mbar_expect_tx(mb_full + buf * 8, CHUNK_BYTES);
                    bulk_ld(sA_u32 + buf * CHUNK_BYTES,
                            src + (long long)kc * CHUNK_BYTES,
                            CHUNK_BYTES, mb_full + buf * 8);
                }
            }
        } else {
            bool rstA = (t + 1 < T_) ? get_reset_m(resets, (t + 1) * B_ + grow0, rmode) : false;
            bool rstB = (t + 1 < T_) ? get_reset_m(resets, (t + 1) * B_ + grow1, rmode) : false;

            // ---- mainloop: 8 chunks, 6 chains (3 gates x kk parity)
            float acc[6][4];
            #pragma unroll
            for (int i = 0; i < 6; i++)
                #pragma unroll
                for (int q = 0; q < 4; q++) acc[i][q] = 0.0f;

            for (int kc = 0; kc < NCHUNK; kc++) {
                const int buf = kc & (NRING - 1);
                mbar_wait(mb_full + buf * 8, (ph_full >> buf) & 1u);
                ph_full ^= 1u << buf;

                const unsigned aB = sA_u32 + buf * CHUNK_BYTES;
                #pragma unroll
                for (int kk = 0; kk < 8; kk++) {
                    unsigned ah[4];
                    ldsm_x4(ah, aB + a_off + kk * 32);
                    unsigned bbase = sW_u32 + b_half +
                                     (unsigned)(kc * 128 + kk * 16) * 48u;
                    unsigned b01[4], b2[2];
                    ldsm_x4t(b01, bbase + b_lane4);        // tn0 (n0-7) + tn1 (n8-15)
                    ldsm_x2t(b2,  bbase + 32 + b_lane);    // tn2 (n16-23)
                    mma16816h(acc[0 * 2 + (kk & 1)], ah, b01 + 0);
                    mma16816h(acc[1 * 2 + (kk & 1)], ah, b01 + 2);
                    mma16816h(acc[2 * 2 + (kk & 1)], ah, b2);
                }
                if (lid == 0) mbar_arrive(mb_empty + buf * 8);
            }

            float gh[3][4];
            #pragma unroll
            for (int tn = 0; tn < 3; tn++)
                #pragma unroll
                for (int q = 0; q < 4; q++)
                    gh[tn][q] = acc[tn * 2][q] + acc[tn * 2 + 1][q];

            // ---- epilogue (register-local; hp carried)
            float hA0, hA1, hB0, hB1;
            {
                float r = 1.f / (1.f + __expf(-(gr0.x + gh[0][0])));
                float z = 1.f / (1.f + __expf(-(gz0.x + gh[1][0])));
                float n = tanhf(gn0.x + r * (gh[2][0] + bj0));
                hA0 = (1.f - z) * n + z * hpA.x;
            }
            {
                float r = 1.f / (1.f + __expf(-(gr0.y + gh[0][1])));
                float z = 1.f / (1.f + __expf(-(gz0.y + gh[1][1])));
                float n = tanhf(gn0.y + r * (gh[2][1] + bj1));
                hA1 = (1.f - z) * n + z * hpA.y;
            }
            {
                float r = 1.f / (1.f + __expf(-(gr1.x + gh[0][2])));
                float z = 1.f / (1.f + __expf(-(gz1.x + gh[1][2])));
                float n = tanhf(gn1.x + r * (gh[2][2] + bj0));
                hB0 = (1.f - z) * n + z * hpB.x;
            }
            {
                float r = 1.f / (1.f + __expf(-(gr1.y + gh[0][3])));
                float z = 1.f / (1.f + __expf(-(gz1.y + gh[1][3])));
                float n = tanhf(gn1.y + r * (gh[2][3] + bj1));
                hB1 = (1.f - z) * n + z * hpB.y;
            }

            if (t + 1 < T_) {
                // masked h store FIRST (epoch release covers this)
                __half* hdst = g_h[(t + 1) & 1] + rg * HGRP_ELEMS;
                float mA0 = rstA ? 0.f : hA0, mA1 = rstA ? 0.f : hA1;
                float mB0 = rstB ? 0.f : hB0, mB1 = rstB ? 0.f : hB1;
                __half2 sv0 = __floats2half2_rn(mA0, mA1);
                __half2 sv1 = __floats2half2_rn(mB0, mB1);
                *(unsigned*)(hdst + hb0) = *reinterpret_cast<unsigned*>(&sv0);
                *(unsigned*)(hdst + hb1) = *reinterpret_cast<unsigned*>(&sv1);
                hpA = __half22float2(sv0);
                hpB = __half22float2(sv1);

                __threadfence();
                asm volatile("bar.sync 1, 256;" ::: "memory");
                if (tid == 0) atomicAdd(&g_bar, 1u);
            }

            // out store + next-step gi prefetch: hidden under the TMA refill
            float* outp = out + (long long)t * B_ * H_;
            *(float2*)(outp + (long long)grow0 * H_ + col) = make_float2(hA0, hA1);
            *(float2*)(outp + (long long)grow1 * H_ + col) = make_float2(hB0, hB1);

            if (t + 1 < T_) {
                const float* gp0 = g_Gi + (long long)(t + 1) * B_ * G3H
                                 + (long long)grow0 * G3H + col;
                const float* gp1 = g_Gi + (long long)(t + 1) * B_ * G3H
                                 + (long long)grow1 * G3H + col;
                gr0 = __ldcs((const float2*)gp0);
                gz0 = __ldcs((const float2*)(gp0 + H_));
                gn0 = __ldcs((const float2*)(gp0 + 2 * H_));
                gr1 = __ldcs((const float2*)gp1);
                gz1 = __ldcs((const float2*)(gp1 + H_));
                gn1 = __ldcs((const float2*)(gp1 + 2 * H_));
            }
        }
    }
}

// ---------------------------------------------------------------------------
extern "C" void kernel_launch(void* const* d_in, const int* in_sizes, int n_in,
                              void* d_out, int out_size)
{
    const float* x      = (const float*)d_in[0];
    const void*  resets = d_in[1];
    const float* h0     = (const float*)d_in[2];
    const float* Wi     = (const float*)d_in[3];
    const float* bi     = (const float*)d_in[4];
    const float* Wh     = (const float*)d_in[5];
    const float* bhn    = (const float*)d_in[6];
    float* out = (float*)d_out;

    cudaFuncSetAttribute(scan_kernel, cudaFuncAttributeMaxDynamicSharedMemorySize,
                         SMEM_TOTAL);

    init_kernel<<<1, 1>>>((const unsigned char*)resets);
    prep_h_kernel<<<(B_ * H_) / 256, 256>>>(h0, resets);
    gi_gemm_kernel<<<dim3(G3H / NT, (T_ * B_) / MT), 256>>>(x, Wi, bi);
    scan_kernel<<<NCTA, NTHREADS, SMEM_TOTAL>>>(Wh, bhn, resets, out);
}

// round 16
// speedup vs baseline: 2.3151x; 1.0077x over previous
#include <cuda_runtime.h>
#include <cuda_bf16.h>
#include <cuda_fp16.h>
#include <mma.h>
#include <cstdint>

using namespace nvcuda;

#define T_   512
#define B_   128
#define D_   512
#define H_   1024
#define G3H  3072

// ---- gi_gemm tiling (proven fp16 single-plane) ----
#define MT   128
#define NT   64
#define KT   32
#define PADA 40
#define PADB 72

// ---- scan: 2 row-groups x 64 col-groups; CTA = [64 rows x 16 cols], fp16 ----
#define NCTA    128
#define RROWS   64
#define SKT     256
#define NCHUNK  (H_ / SKT)                  // 4
#define NRING   3
#define A_LD    264                         // fp16 elems/row (528B, conflict-free)
#define CHUNK_ELEMS (RROWS * A_LD)          // 16896
#define CHUNK_BYTES (CHUNK_ELEMS * 2)       // 33792
#define HGRP_ELEMS (NCHUNK * CHUNK_ELEMS)
#define B_LD    24
#define BHALF_BYTES (H_ * B_LD * 2)         // 49152
#define SM_W    0
#define SM_A    (2 * BHALF_BYTES)           // 98304
#define SM_CTL  (SM_A + NRING * CHUNK_BYTES) // 199680
#define SMEM_TOTAL (SM_CTL + 64)
#define NTHREADS 288

__device__ __align__(256) float  g_Gi[(long long)T_ * B_ * G3H];
// h scratch: [pingpong][rowgroup][chunk][64][264] fp16
__device__ __align__(256) __half g_h[2][2 * HGRP_ELEMS];
__device__ int      g_reset_mode;
__device__ __align__(128) unsigned g_barr[2 * 32];   // per-rowgroup epoch, 128B apart

// ---------------------------------------------------------------------------
__global__ void init_kernel(const unsigned char* __restrict__ resets) {
    const unsigned int* w = (const unsigned int*)resets;
    bool i32 = true, f32 = true;
    for (int i = 0; i < 16; i++) {
        unsigned int v = w[i];
        if (v != 0u && v != 1u) i32 = false;
        if (v != 0u && v != 0x3F800000u) f32 = false;
    }
    g_reset_mode = i32 ? 1 : (f32 ? 2 : 0);
    g_barr[0] = 0u;
    g_barr[32] = 0u;
}

__device__ __forceinline__ bool get_reset_m(const void* r, int idx, int m) {
    if (m == 1) return ((const int*)r)[idx] != 0;
    if (m == 2) return ((const float*)r)[idx] != 0.0f;
    return ((const unsigned char*)r)[idx] != 0;
}

__device__ __forceinline__ unsigned smem_u32(const void* p) {
    return (unsigned)__cvta_generic_to_shared(p);
}
__device__ __forceinline__ void mbar_init(unsigned a, unsigned c) {
    asm volatile("mbarrier.init.shared.b64 [%0], %1;" :: "r"(a), "r"(c) : "memory");
}
__device__ __forceinline__ void mbar_arrive(unsigned a) {
    asm volatile("mbarrier.arrive.shared.b64 _, [%0];" :: "r"(a) : "memory");
}
__device__ __forceinline__ void mbar_expect_tx(unsigned a, unsigned bytes) {
    asm volatile("mbarrier.arrive.expect_tx.shared.b64 _, [%0], %1;"
                 :: "r"(a), "r"(bytes) : "memory");
}
__device__ __forceinline__ void mbar_wait(unsigned a, unsigned parity) {
    asm volatile(
        "{\n\t.reg .pred P;\n\t"
        "W_%=:\n\t"
        "mbarrier.try_wait.parity.acquire.cta.shared::cta.b64 P, [%0], %1, 0x989680;\n\t"
        "@P bra D_%=;\n\t"
        "bra.uni W_%=;\n\t"
        "D_%=:\n\t}"
        :: "r"(a), "r"(parity) : "memory");
}
__device__ __forceinline__ void bulk_ld(unsigned dst, const void* src,
                                        unsigned bytes, unsigned mbar) {
    asm volatile(
        "cp.async.bulk.shared::cta.global.mbarrier::complete_tx::bytes [%0], [%1], %2, [%3];"
        :: "r"(dst), "l"(src), "r"(bytes), "r"(mbar) : "memory");
}
__device__ __forceinline__ unsigned ld_acquire(const unsigned* p) {
    unsigned v;
    asm volatile("ld.acquire.gpu.u32 %0, [%1];" : "=r"(v) : "l"(p) : "memory");
    return v;
}
__device__ __forceinline__ void fence_release() {
    asm volatile("fence.acq_rel.gpu;" ::: "memory");
}

__device__ __forceinline__ void ldsm_x4(unsigned* r, unsigned a) {
    asm volatile("ldmatrix.sync.aligned.m8n8.x4.shared.b16 {%0,%1,%2,%3}, [%4];"
                 : "=r"(r[0]), "=r"(r[1]), "=r"(r[2]), "=r"(r[3]) : "r"(a));
}
__device__ __forceinline__ void ldsm_x4t(unsigned* r, unsigned a) {
    asm volatile("ldmatrix.sync.aligned.m8n8.x4.trans.shared.b16 {%0,%1,%2,%3}, [%4];"
                 : "=r"(r[0]), "=r"(r[1]), "=r"(r[2]), "=r"(r[3]) : "r"(a));
}
__device__ __forceinline__ void ldsm_x2t(unsigned* r, unsigned a) {
    asm volatile("ldmatrix.sync.aligned.m8n8.x2.trans.shared.b16 {%0,%1}, [%2];"
                 : "=r"(r[0]), "=r"(r[1]) : "r"(a));
}
__device__ __forceinline__ void mma16816h(float* c, const unsigned* a, const unsigned* b) {
    asm volatile(
        "mma.sync.aligned.m16n8k16.row.col.f32.f16.f16.f32 "
        "{%0,%1,%2,%3}, {%4,%5,%6,%7}, {%8,%9}, {%0,%1,%2,%3};"
        : "+f"(c[0]), "+f"(c[1]), "+f"(c[2]), "+f"(c[3])
        : "r"(a[0]), "r"(a[1]), "r"(a[2]), "r"(a[3]), "r"(b[0]), "r"(b[1]));
}

__global__ void prep_h_kernel(const float* __restrict__ h0,
                              const void* __restrict__ resets)
{
    int i = blockIdx.x * 256 + threadIdx.x;    // 0 .. B*H-1
    int b = i >> 10;
    int k = i & 1023;
    float v = get_reset_m(resets, b, g_reset_mode) ? 0.0f : h0[i];
    int rg = b >> 6;
    int r  = b & 63;
    int o = rg * HGRP_ELEMS + (k >> 8) * CHUNK_ELEMS + r * A_LD + (k & 255);
    g_h[0][o] = __float2half_rn(v);
}

// ---------------------------------------------------------------------------
// Phase B: Gi = X @ Wi + bi   (proven, fp16 single-plane, verbatim)
// ---------------------------------------------------------------------------
__global__ __launch_bounds__(256) void gi_gemm_kernel(
    const float* __restrict__ X,
    const float* __restrict__ Wi,
    const float* __restrict__ bi)
{
    __shared__ __align__(16) __half sA[MT * PADA];
    __shared__ __align__(16) __half sB[KT * PADB];
    __shared__ __align__(16) float sBias[16 * NT];

    const int n0  = blockIdx.x * NT;
    const long long m0 = (long long)blockIdx.y * MT;
    const int tid  = threadIdx.x;
    const int warp = tid >> 5;
    const int wm   = warp & 3;
    const int wn   = warp >> 2;

    for (int i = tid; i < 16 * NT; i += 256) sBias[i] = bi[n0 + (i % NT)];
    __syncthreads();

    wmma::fragment<wmma::accumulator, 16, 16, 16, float> acc[2][2];
    for (int i = 0; i < 2; i++)
        for (int j = 0; j < 2; j++)
            wmma::load_matrix_sync(acc[i][j], &sBias[wn * 32 + j * 16], NT,
                                   wmma::mem_row_major);

    for (int k0 = 0; k0 < D_; k0 += KT) {
        __syncthreads();
        for (int i = tid; i < MT * KT / 4; i += 256) {
            int r = i >> 3;
            int c = (i & 7) * 4;
            float4 v = *(const float4*)(X + (m0 + r) * D_ + k0 + c);
            sA[r * PADA + c + 0] = __float2half_rn(v.x);
            sA[r * PADA + c + 1] = __float2half_rn(v.y);
            sA[r * PADA + c + 2] = __float2half_rn(v.z);
            sA[r * PADA + c + 3] = __float2half_rn(v.w);
        }
        for (int i = tid; i < KT * NT / 4; i += 256) {
            int r = i >> 4;
            int c = (i & 15) * 4;
            float4 v = *(const float4*)(Wi + (long long)(k0 + r) * G3H + n0 + c);
            sB[r * PADB + c + 0] = __float2half_rn(v.x);
            sB[r * PADB + c + 1] = __float2half_rn(v.y);
            sB[r * PADB + c + 2] = __float2half_rn(v.z);
            sB[r * PADB + c + 3] = __float2half_rn(v.w);
        }
        __syncthreads();

        #pragma unroll
        for (int kk = 0; kk < KT; kk += 16) {
            wmma::fragment<wmma::matrix_a, 16, 16, 16, __half, wmma::row_major> a[2];
            wmma::fragment<wmma::matrix_b, 16, 16, 16, __half, wmma::row_major> b[2];
            #pragma unroll
            for (int i = 0; i < 2; i++)
                wmma::load_matrix_sync(a[i], &sA[(wm * 32 + i * 16) * PADA + kk], PADA);
            #pragma unroll
            for (int j = 0; j < 2; j++)
                wmma::load_matrix_sync(b[j], &sB[kk * PADB + wn * 32 + j * 16], PADB);
            #pragma unroll
            for (int i = 0; i < 2; i++)
                #pragma unroll
                for (int j = 0; j < 2; j++)
                    wmma::mma_sync(acc[i][j], a[i], b[j], acc[i][j]);
        }
    }

    for (int i = 0; i < 2; i++)
        for (int j = 0; j < 2; j++) {
            float* p = g_Gi + (m0 + wm * 32 + i * 16) * G3H + n0 + wn * 32 + j * 16;
            wmma::store_matrix_sync(p, acc[i][j], G3H, wmma::mem_row_major);
        }
}

// ---------------------------------------------------------------------------
// Persistent scan (fp16x1, SKT=256): 128 CTAs x 288 threads.
// Producer-only epoch wait, PER-ROW-GROUP epochs (64-CTA convergence).
// ---------------------------------------------------------------------------
__global__ __launch_bounds__(NTHREADS, 1) void scan_kernel(
    const float* __restrict__ Wh,
    const float* __restrict__ bhn,
    const void*  __restrict__ resets,
    float*       __restrict__ out)
{
    extern __shared__ __align__(128) char sm[];
    __half* sW = (__half*)(sm + SM_W);
    const unsigned sW_u32 = smem_u32(sm + SM_W);
    const unsigned sA_u32 = smem_u32(sm + SM_A);
    const unsigned ctl      = smem_u32(sm + SM_CTL);
    const unsigned mb_full  = ctl;        // 3 x 8B
    const unsigned mb_empty = ctl + 24;   // 3 x 8B

    const int tid = threadIdx.x;
    const int wid = tid >> 5;
    const int lid = tid & 31;
    const int bid = blockIdx.x;
    const int rg  = bid >> 6;
    const int j0  = (bid & 63) * 16;
    const int rmode = g_reset_mode;
    unsigned* epoch = &g_barr[rg * 32];

    // ---- load resident Wh slice: 48 packed cols (fp16)
    for (int idx = tid; idx < H_ * 48; idx += NTHREADS) {
        int k = idx / 48;
        int c = idx - k * 48;
        int h = c >= 24;
        int cr = c - h * 24;
        int g  = cr >> 3;
        int cj = cr & 7;
        float v = Wh[(long long)k * G3H + g * H_ + j0 + h * 8 + cj];
        sW[h * (H_ * B_LD) + k * B_LD + cr] = __float2half_rn(v);
    }

    if (tid == 0) {
        #pragma unroll
        for (int i = 0; i < NRING; i++) {
            mbar_init(mb_full + i * 8, 1);
            mbar_init(mb_empty + i * 8, 8);
        }
    }
    __syncthreads();
    if (tid < 8) {
        #pragma unroll
        for (int i = 0; i < NRING; i++) mbar_arrive(mb_empty + i * 8);
    }
    asm volatile("fence.proxy.async;" ::: "memory");
    __syncthreads();

    // consumer geometry (SKT=256: 528B A rows, kk 0..15)
    const int wm = wid & 3;
    const int nh = (wid >> 2) & 1;
    const unsigned a_off = (unsigned)((wm * 16 + (lid & 15)) * 528 + (lid >> 4) * 16);
    const unsigned b_half = (unsigned)(nh * BHALF_BYTES);
    const unsigned b_lane  = (unsigned)((lid & 15) * 48);
    const unsigned b_lane4 = (unsigned)(((lid >> 4) & 1) * 16 + (lid & 15) * 48);

    // epilogue coords
    const int r0l = wm * 16 + (lid >> 2);
    const int r1l = r0l + 8;
    const int grow0 = rg * 64 + r0l;
    const int grow1 = rg * 64 + r1l;
    const int col = j0 + nh * 8 + (lid & 3) * 2;
    const int hb0 = (col >> 8) * CHUNK_ELEMS + r0l * A_LD + (col & 255);
    const int hb1 = (col >> 8) * CHUNK_ELEMS + r1l * A_LD + (col & 255);
    float bj0 = bhn[col], bj1 = bhn[col + 1];

    unsigned ph_empty = 0;
    unsigned ph_full  = 0;

    // ---- pre-loop prefetch (t=0): gi + hp
    float2 gr0, gz0, gn0, gr1, gz1, gn1;
    float2 hpA, hpB;
    if (wid < 8) {
        const float* gp0 = g_Gi + (long long)grow0 * G3H + col;
        const float* gp1 = g_Gi + (long long)grow1 * G3H + col;
        gr0 = __ldcs((const float2*)gp0);
        gz0 = __ldcs((const float2*)(gp0 + H_));
        gn0 = __ldcs((const float2*)(gp0 + 2 * H_));
        gr1 = __ldcs((const float2*)gp1);
        gz1 = __ldcs((const float2*)(gp1 + H_));
        gn1 = __ldcs((const float2*)(gp1 + 2 * H_));
        const __half* h0p = g_h[0] + rg * HGRP_ELEMS;
        unsigned hh0 = *(const unsigned*)(h0p + hb0);
        unsigned hh1 = *(const unsigned*)(h0p + hb1);
        hpA = __half22float2(*reinterpret_cast<__half2*>(&hh0));
        hpB = __half22float2(*reinterpret_cast<__half2*>(&hh1));
    }

    for (int t = 0; t < T_; t++) {
        if (wid == 8) {
            if (lid == 0) {
                if (t > 0) {
                    const unsigned target = 64u * (unsigned)t;
                    while (ld_acquire(epoch) < target) { }
                }
                const char* src = (const char*)(g_h[t & 1] + rg * HGRP_ELEMS);
                for (int kc = 0; kc < NCHUNK; kc++) {
                    int buf = kc - (kc / 3) * 3;
                    mbar_wait(mb_empty + buf * 8, (ph_empty >> buf) & 1u);
                    ph_empty ^= 1u << buf;
                    mbar_expect_tx(mb_full + buf * 8, CHUNK_BYTES);
                    bulk_ld(sA_u32 + buf * CHUNK_BYTES,
                            src + (long long)kc * CHUNK_BYTES,
                            CHUNK_BYTES, mb_full + buf * 8);
                }
            }
        } else {
            bool rstA = (t + 1 < T_) ? get_reset_m(resets, (t + 1) * B_ + grow0, rmode) : false;
            bool rstB = (t + 1 < T_) ? get_reset_m(resets, (t + 1) * B_ + grow1, rmode) : false;

            // ---- mainloop: 4 chunks, 6 chains (3 gates x kk parity)
            float acc[6][4];
            #pragma unroll
            for (int i = 0; i < 6; i++)
                #pragma unroll
                for (int q = 0; q < 4; q++) acc[i][q] = 0.0f;

            for (int kc = 0; kc < NCHUNK; kc++) {
                const int buf = kc - (kc / 3) * 3;
                mbar_wait(mb_full + buf * 8, (ph_full >> buf) & 1u);
                ph_full ^= 1u << buf;

                const unsigned aB = sA_u32 + buf * CHUNK_BYTES;
                #pragma unroll
                for (int kk = 0; kk < 16; kk++) {
                    unsigned ah[4];
                    ldsm_x4(ah, aB + a_off + kk * 32);
                    unsigned bbase = sW_u32 + b_half +
                                     (unsigned)(kc * 256 + kk * 16) * 48u;
                    unsigned b01[4], b2[2];
                    ldsm_x4t(b01, bbase + b_lane4);
                    ldsm_x2t(b2,  bbase + 32 + b_lane);
                    mma16816h(acc[0 * 2 + (kk & 1)], ah, b01 + 0);
                    mma16816h(acc[1 * 2 + (kk & 1)], ah, b01 + 2);
                    mma16816h(acc[2 * 2 + (kk & 1)], ah, b2);
                }
                if (lid == 0) mbar_arrive(mb_empty + buf * 8);
            }

            float gh[3][4];
            #pragma unroll
            for (int tn = 0; tn < 3; tn++)
                #pragma unroll
                for (int q = 0; q < 4; q++)
                    gh[tn][q] = acc[tn * 2][q] + acc[tn * 2 + 1][q];

            // ---- epilogue (register-local; hp carried)
            float hA0, hA1, hB0, hB1;
            {
                float r = 1.f / (1.f + __expf(-(gr0.x + gh[0][0])));
                float z = 1.f / (1.f + __expf(-(gz0.x + gh[1][0])));
                float n = tanhf(gn0.x + r * (gh[2][0] + bj0));
                hA0 = (1.f - z) * n + z * hpA.x;
            }
            {
                float r = 1.f / (1.f + __expf(-(gr0.y + gh[0][1])));
                float z = 1.f / (1.f + __expf(-(gz0.y + gh[1][1])));
                float n = tanhf(gn0.y + r * (gh[2][1] + bj1));
                hA1 = (1.f - z) * n + z * hpA.y;
            }
            {
                float r = 1.f / (1.f + __expf(-(gr1.x + gh[0][2])));
                float z = 1.f / (1.f + __expf(-(gz1.x + gh[1][2])));
                float n = tanhf(gn1.x + r * (gh[2][2] + bj0));
                hB0 = (1.f - z) * n + z * hpB.x;
            }
            {
                float r = 1.f / (1.f + __expf(-(gr1.y + gh[0][3])));
                float z = 1.f / (1.f + __expf(-(gz1.y + gh[1][3])));
                float n = tanhf(gn1.y + r * (gh[2][3] + bj1));
                hB1 = (1.f - z) * n + z * hpB.y;
            }

            if (t + 1 < T_) {
                // masked h store FIRST (epoch release covers this)
                __half* hdst = g_h[(t + 1) & 1] + rg * HGRP_ELEMS;
                float mA0 = rstA ? 0.f : hA0, mA1 = rstA ? 0.f : hA1;
                float mB0 = rstB ? 0.f : hB0, mB1 = rstB ? 0.f : hB1;
                __half2 sv0 = __floats2half2_rn(mA0, mA1);
                __half2 sv1 = __floats2half2_rn(mB0, mB1);
                *(unsigned*)(hdst + hb0) = *reinterpret_cast<unsigned*>(&sv0);
                *(unsigned*)(hdst + hb1) = *reinterpret_cast<unsigned*>(&sv1);
                hpA = __half22float2(sv0);
                hpB = __half22float2(sv1);

                fence_release();
                asm volatile("bar.sync 1, 256;" ::: "memory");
                if (tid == 0) atomicAdd(epoch, 1u);
            }

            // out store + next-step gi prefetch: hidden under the TMA refill
            float* outp = out + (long long)t * B_ * H_;
            *(float2*)(outp + (long long)grow0 * H_ + col) = make_float2(hA0, hA1);
            *(float2*)(outp + (long long)grow1 * H_ + col) = make_float2(hB0, hB1);

            if (t + 1 < T_) {
                const float* gp0 = g_Gi + (long long)(t + 1) * B_ * G3H
                                 + (long long)grow0 * G3H + col;
                const float* gp1 = g_Gi + (long long)(t + 1) * B_ * G3H
                                 + (long long)grow1 * G3H + col;
                gr0 = __ldcs((const float2*)gp0);
                gz0 = __ldcs((const float2*)(gp0 + H_));
                gn0 = __ldcs((const float2*)(gp0 + 2 * H_));
                gr1 = __ldcs((const float2*)gp1);
                gz1 = __ldcs((const float2*)(gp1 + H_));
                gn1 = __ldcs((const float2*)(gp1 + 2 * H_));
            }
        }
    }
}

// ---------------------------------------------------------------------------
extern "C" void kernel_launch(void* const* d_in, const int* in_sizes, int n_in,
                              void* d_out, int out_size)
{
    const float* x      = (const float*)d_in[0];
    const void*  resets = d_in[1];
    const float* h0     = (const float*)d_in[2];
    const float* Wi     = (const float*)d_in[3];
    const float* bi     = (const float*)d_in[4];
    const float* Wh     = (const float*)d_in[5];
    const float* bhn    = (const float*)d_in[6];
    float* out = (float*)d_out;

    cudaFuncSetAttribute(scan_kernel, cudaFuncAttributeMaxDynamicSharedMemorySize,
                         SMEM_TOTAL);

    init_kernel<<<1, 1>>>((const unsigned char*)resets);
    prep_h_kernel<<<(B_ * H_) / 256, 256>>>(h0, resets);
    gi_gemm_kernel<<<dim3(G3H / NT, (T_ * B_) / MT), 256>>>(x, Wi, bi);
    scan_kernel<<<NCTA, NTHREADS, SMEM_TOTAL>>>(Wh, bhn, resets, out);
}